// round 2
// baseline (speedup 1.0000x reference)
#include <cuda_runtime.h>

#define B    8
#define NN   2048
#define FIN  128
#define FOUT 64

// Scratch (no cudaMalloc allowed)
__device__ __align__(16) float g_Wh[B * NN * FOUT];
__device__ __align__(16) float g_s1[B * NN];
__device__ __align__(16) float g_s2[B * NN];

// ---------------------------------------------------------------------------
// Fast exp on the FMA pipe (no MUFU). Magic-number round + deg-6 Taylor.
// Valid for |x| < ~80; here x in [-4, 16]. rel err ~2e-6.
// ---------------------------------------------------------------------------
__device__ __forceinline__ float fexp(float x) {
    float z  = fmaf(x, 1.4426950408889634f, 12582912.0f);  // 1.5*2^23 magic
    int   n  = __float_as_int(z) - 0x4B400000;             // rint(x*log2e)
    float zf = z - 12582912.0f;
    float r  = fmaf(zf, -0.6931471805599453f, x);          // |r| <= 0.3466
    float p  =        1.3888889e-3f;
    p = fmaf(p, r,    8.3333333e-3f);
    p = fmaf(p, r,    4.1666668e-2f);
    p = fmaf(p, r,    1.6666667e-1f);
    p = fmaf(p, r,    5.0000000e-1f);
    p = fmaf(p, r,    1.0f);
    p = fmaf(p, r,    1.0f);
    return __int_as_float(__float_as_int(p) + (n << 23));  // p * 2^n
}

// packed f32x2 helpers (sm_103a)
__device__ __forceinline__ void fma2(unsigned long long& d,
                                     unsigned long long a,
                                     unsigned long long b) {
    asm("fma.rn.f32x2 %0, %1, %2, %0;" : "+l"(d) : "l"(a), "l"(b));
}
__device__ __forceinline__ unsigned long long bcast2(float v) {
    unsigned long long r;
    asm("mov.b64 %0, {%1, %1};" : "=l"(r) : "f"(v));
    return r;
}

// ---------------------------------------------------------------------------
// Kernel 1: Wh = h @ W^T fused with s1 = Wh@a1, s2 = Wh@a2.
// 128 threads, 32 rows/CTA, grid 512. W^T staged in smem; h read via
// broadcast LDG (16 lanes share each address -> 1 sector).
// ---------------------------------------------------------------------------
__global__ __launch_bounds__(128) void wh_kernel(const float* __restrict__ h,
                                                 const float* __restrict__ W,
                                                 const float* __restrict__ a) {
    __shared__ float Wt[FIN][FOUT];  // 32 KB, Wt[f][o] = W[o][f]
    int tid  = threadIdx.x;
    int row0 = blockIdx.x * 32;

    for (int idx = tid; idx < FIN * FOUT; idx += 128) {
        int f = idx >> 6, o = idx & 63;
        Wt[f][o] = W[o * FIN + f];
    }
    __syncthreads();

    int rg = tid >> 4, cg = tid & 15;
    int r0 = row0 + rg * 4;     // 4 global rows per thread
    int c0 = cg * 4;            // 4 output cols per thread

    float acc[4][4] = {};
    for (int f = 0; f < FIN; f += 4) {
        float4 wv0 = *(const float4*)&Wt[f + 0][c0];
        float4 wv1 = *(const float4*)&Wt[f + 1][c0];
        float4 wv2 = *(const float4*)&Wt[f + 2][c0];
        float4 wv3 = *(const float4*)&Wt[f + 3][c0];
#pragma unroll
        for (int k = 0; k < 4; k++) {
            float4 hv = __ldg((const float4*)&h[(size_t)(r0 + k) * FIN + f]);
            acc[k][0] += hv.x * wv0.x + hv.y * wv1.x + hv.z * wv2.x + hv.w * wv3.x;
            acc[k][1] += hv.x * wv0.y + hv.y * wv1.y + hv.z * wv2.y + hv.w * wv3.y;
            acc[k][2] += hv.x * wv0.z + hv.y * wv1.z + hv.z * wv2.z + hv.w * wv3.z;
            acc[k][3] += hv.x * wv0.w + hv.y * wv1.w + hv.z * wv2.w + hv.w * wv3.w;
        }
    }

    float a1x = __ldg(&a[c0]),      a1y = __ldg(&a[c0 + 1]);
    float a1z = __ldg(&a[c0 + 2]),  a1w = __ldg(&a[c0 + 3]);
    float a2x = __ldg(&a[64 + c0]),     a2y = __ldg(&a[64 + c0 + 1]);
    float a2z = __ldg(&a[64 + c0 + 2]), a2w = __ldg(&a[64 + c0 + 3]);

#pragma unroll
    for (int k = 0; k < 4; k++) {
        // write Wh row chunk
        float4 o4 = make_float4(acc[k][0], acc[k][1], acc[k][2], acc[k][3]);
        *(float4*)&g_Wh[(size_t)(r0 + k) * FOUT + c0] = o4;
        // s1/s2 partials, reduce over the 16 cg lanes
        float t1 = acc[k][0] * a1x + acc[k][1] * a1y + acc[k][2] * a1z + acc[k][3] * a1w;
        float t2 = acc[k][0] * a2x + acc[k][1] * a2y + acc[k][2] * a2z + acc[k][3] * a2w;
        t1 += __shfl_xor_sync(0xffffffffu, t1, 8);
        t1 += __shfl_xor_sync(0xffffffffu, t1, 4);
        t1 += __shfl_xor_sync(0xffffffffu, t1, 2);
        t1 += __shfl_xor_sync(0xffffffffu, t1, 1);
        t2 += __shfl_xor_sync(0xffffffffu, t2, 8);
        t2 += __shfl_xor_sync(0xffffffffu, t2, 4);
        t2 += __shfl_xor_sync(0xffffffffu, t2, 2);
        t2 += __shfl_xor_sync(0xffffffffu, t2, 1);
        if (cg == 0) {
            g_s1[r0 + k] = t1;
            g_s2[r0 + k] = t2;
        }
    }
}

// ---------------------------------------------------------------------------
// Kernel 2: fused masked-softmax attention + P@Wh.
// CTA = 64 query rows of one batch, 128 threads, J streamed in tiles of 64.
// Stage 1: build P tile with FMA-pipe exp; per-row denominators kept in
//          registers (butterfly shuffle leaves sum in all 16 lanes).
// Stage 2: 8x4 thread tile, column-paired fma.rn.f32x2 (FFMA2).
// ---------------------------------------------------------------------------
__global__ __launch_bounds__(128) void attn_kernel(const int* __restrict__ adj,
                                                   float* __restrict__ out) {
    __shared__ float Ps[64][64];   // 16 KB  unnormalized attention tile
    __shared__ float Vs[64][64];   // 16 KB  Wh tile
    __shared__ float s1s[64];

    int b   = blockIdx.y;
    int i0  = blockIdx.x * 64;
    int tid = threadIdx.x;
    int jq  = tid & 15;            // stage1: 4 j's ; stage2: col group
    int iw  = tid >> 4;            // stage1/2: rows iw*8 .. iw*8+7
    int c0  = jq * 4;

    if (tid < 64) s1s[tid] = g_s1[b * NN + i0 + tid];

    const float*  s2b   = g_s2 + b * NN;
    const float4* wh_b  = (const float4*)(g_Wh + (size_t)b * NN * FOUT);
    const int*    mbase = adj + (size_t)(b * NN + i0 + iw * 8) * NN + 4 * jq;

    unsigned long long acc2[8][2] = {};  // (c0,c0+1) and (c0+2,c0+3) pairs
    float dsum[8] = {0.f, 0.f, 0.f, 0.f, 0.f, 0.f, 0.f, 0.f};

    for (int j0 = 0; j0 < NN; j0 += 64) {
        __syncthreads();   // previous stage-2 reads complete

        // ---- load V tile (coalesced float4) ----
        for (int idx = tid; idx < 64 * 16; idx += 128) {
            int j = idx >> 4, q = idx & 15;
            ((float4*)&Vs[j][0])[q] = wh_b[(size_t)(j0 + j) * 16 + q];
        }

        // ---- build P tile + register row sums ----
        float4 s2v = *(const float4*)(s2b + j0 + 4 * jq);
#pragma unroll
        for (int k = 0; k < 8; k++) {
            int   i   = iw * 8 + k;
            float s1v = s1s[i];
            int4  m   = *(const int4*)(mbase + (size_t)k * NN + j0);
            float e;
            float4 p;
            e = s1v + s2v.x; e = e > 0.f ? e : 0.2f * e; p.x = m.x ? fexp(e) : 0.f;
            e = s1v + s2v.y; e = e > 0.f ? e : 0.2f * e; p.y = m.y ? fexp(e) : 0.f;
            e = s1v + s2v.z; e = e > 0.f ? e : 0.2f * e; p.z = m.z ? fexp(e) : 0.f;
            e = s1v + s2v.w; e = e > 0.f ? e : 0.2f * e; p.w = m.w ? fexp(e) : 0.f;
            *(float4*)&Ps[i][4 * jq] = p;
            float rs = (p.x + p.y) + (p.z + p.w);
            rs += __shfl_xor_sync(0xffffffffu, rs, 8);
            rs += __shfl_xor_sync(0xffffffffu, rs, 4);
            rs += __shfl_xor_sync(0xffffffffu, rs, 2);
            rs += __shfl_xor_sync(0xffffffffu, rs, 1);
            dsum[k] += rs;   // butterfly leaves the full 16-lane sum everywhere
        }
        __syncthreads();

        // ---- C += P_tile @ V_tile  (FFMA2, column-paired) ----
#pragma unroll 1
        for (int jj = 0; jj < 64; jj += 4) {
            float4 p4[8];
#pragma unroll
            for (int r = 0; r < 8; r++)
                p4[r] = *(const float4*)&Ps[iw * 8 + r][jj];   // broadcast LDS
#pragma unroll
            for (int jo = 0; jo < 4; jo++) {
                ulonglong2 v2 = *(const ulonglong2*)&Vs[jj + jo][c0];
#pragma unroll
                for (int r = 0; r < 8; r++) {
                    float pv = (jo == 0) ? p4[r].x : (jo == 1) ? p4[r].y
                             : (jo == 2) ? p4[r].z : p4[r].w;
                    unsigned long long pp = bcast2(pv);
                    fma2(acc2[r][0], pp, v2.x);
                    fma2(acc2[r][1], pp, v2.y);
                }
            }
        }
    }

    // ---- epilogue: normalize + store ----
#pragma unroll
    for (int k = 0; k < 8; k++) {
        float inv = __fdividef(1.0f, dsum[k]);
        float lx, ly, hx, hy;
        asm("mov.b64 {%0, %1}, %2;" : "=f"(lx), "=f"(ly) : "l"(acc2[k][0]));
        asm("mov.b64 {%0, %1}, %2;" : "=f"(hx), "=f"(hy) : "l"(acc2[k][1]));
        float4 o = make_float4(lx * inv, ly * inv, hx * inv, hy * inv);
        *(float4*)&out[(size_t)(b * NN + i0 + iw * 8 + k) * FOUT + c0] = o;
    }
}

// ---------------------------------------------------------------------------
extern "C" void kernel_launch(void* const* d_in, const int* in_sizes, int n_in,
                              void* d_out, int out_size) {
    const float* h   = (const float*)d_in[0];
    const int*   adj = (const int*)d_in[1];
    const float* W   = (const float*)d_in[2];
    const float* a   = (const float*)d_in[3];
    float* out = (float*)d_out;

    wh_kernel<<<(B * NN) / 32, 128>>>(h, W, a);
    attn_kernel<<<dim3(NN / 64, B), 128>>>(adj, out);
}

// round 3
// speedup vs baseline: 1.1411x; 1.1411x over previous
#include <cuda_runtime.h>

#define B    8
#define NN   2048
#define FIN  128
#define FOUT 64

// Scratch (no cudaMalloc allowed)
__device__ __align__(16) float g_Wh[B * NN * FOUT];
__device__ __align__(16) float g_s1[B * NN];
__device__ __align__(16) float g_s2[B * NN];

// ---------------------------------------------------------------------------
// Fast exp on the FMA pipe (no MUFU). Magic-number round + deg-6 poly.
// Valid for |x| < ~80 (here |x| < ~20). rel err ~2e-6.
// ---------------------------------------------------------------------------
__device__ __forceinline__ float fexp(float x) {
    float z  = fmaf(x, 1.4426950408889634f, 12582912.0f);
    int   n  = __float_as_int(z) - 0x4B400000;
    float zf = z - 12582912.0f;
    float r  = fmaf(zf, -0.6931471805599453f, x);
    float p  =        1.3888889e-3f;
    p = fmaf(p, r,    8.3333333e-3f);
    p = fmaf(p, r,    4.1666668e-2f);
    p = fmaf(p, r,    1.6666667e-1f);
    p = fmaf(p, r,    5.0000000e-1f);
    p = fmaf(p, r,    1.0f);
    p = fmaf(p, r,    1.0f);
    return __int_as_float(__float_as_int(p) + (n << 23));
}

// packed f32x2 FMA (sm_103a FFMA2)
__device__ __forceinline__ void fma2(unsigned long long& d,
                                     unsigned long long a,
                                     unsigned long long b) {
    asm("fma.rn.f32x2 %0, %1, %2, %0;" : "+l"(d) : "l"(a), "l"(b));
}

// ---------------------------------------------------------------------------
// Kernel 1: Wh = h @ W^T fused with s1/s2. 256 thr, 32 rows/CTA, grid 512.
// W staged transposed in smem (pad 68 -> conflict-free vec4 reads).
// ---------------------------------------------------------------------------
__global__ __launch_bounds__(256) void wh_kernel(const float* __restrict__ h,
                                                 const float* __restrict__ W,
                                                 const float* __restrict__ a) {
    __shared__ float Wt[FIN][68];
    int tid = threadIdx.x;
    for (int idx = tid; idx < FOUT * FIN; idx += 256) {
        int o = idx >> 7, f = idx & 127;   // coalesced LDG of W
        Wt[f][o] = W[idx];
    }
    __syncthreads();

    int row0 = blockIdx.x * 32;
    int rg = tid >> 4, cg = tid & 15;
    int r0 = row0 + rg * 2;     // 2 rows per thread
    int c0 = cg * 4;

    float acc[2][4] = {};
    const float* hp = h + (size_t)r0 * FIN;
    for (int f = 0; f < FIN; f += 4) {
        float4 wv0 = *(const float4*)&Wt[f + 0][c0];
        float4 wv1 = *(const float4*)&Wt[f + 1][c0];
        float4 wv2 = *(const float4*)&Wt[f + 2][c0];
        float4 wv3 = *(const float4*)&Wt[f + 3][c0];
#pragma unroll
        for (int k = 0; k < 2; k++) {
            float4 hv = __ldg((const float4*)(hp + k * FIN + f));
            acc[k][0] += hv.x * wv0.x + hv.y * wv1.x + hv.z * wv2.x + hv.w * wv3.x;
            acc[k][1] += hv.x * wv0.y + hv.y * wv1.y + hv.z * wv2.y + hv.w * wv3.y;
            acc[k][2] += hv.x * wv0.z + hv.y * wv1.z + hv.z * wv2.z + hv.w * wv3.z;
            acc[k][3] += hv.x * wv0.w + hv.y * wv1.w + hv.z * wv2.w + hv.w * wv3.w;
        }
    }

    float a1x = __ldg(&a[c0]),          a1y = __ldg(&a[c0 + 1]);
    float a1z = __ldg(&a[c0 + 2]),      a1w = __ldg(&a[c0 + 3]);
    float a2x = __ldg(&a[64 + c0]),     a2y = __ldg(&a[64 + c0 + 1]);
    float a2z = __ldg(&a[64 + c0 + 2]), a2w = __ldg(&a[64 + c0 + 3]);

#pragma unroll
    for (int k = 0; k < 2; k++) {
        *(float4*)&g_Wh[(size_t)(r0 + k) * FOUT + c0] =
            make_float4(acc[k][0], acc[k][1], acc[k][2], acc[k][3]);
        float t1 = acc[k][0] * a1x + acc[k][1] * a1y + acc[k][2] * a1z + acc[k][3] * a1w;
        float t2 = acc[k][0] * a2x + acc[k][1] * a2y + acc[k][2] * a2z + acc[k][3] * a2w;
#pragma unroll
        for (int ofs = 8; ofs >= 1; ofs >>= 1) {
            t1 += __shfl_xor_sync(0xffffffffu, t1, ofs);
            t2 += __shfl_xor_sync(0xffffffffu, t2, ofs);
        }
        if (cg == 0) {
            g_s1[r0 + k] = t1;
            g_s2[r0 + k] = t2;
        }
    }
}

// ---------------------------------------------------------------------------
// Kernel 2: fused masked-softmax attention + P@Wh.
// 256 threads, 64x64 I-tile, J streamed in tiles of 64.
// P stored in smem pre-duplicated as (p,p) float2 pairs -> stage-2 GEMM is
// pure LDS.128 + FFMA2 (no packing MOVs). Denominators live in registers;
// one butterfly at the very end. Mask/s2 loads software-pipelined.
// ---------------------------------------------------------------------------
__global__ __launch_bounds__(256, 2) void attn_kernel(const int* __restrict__ adj,
                                                      float* __restrict__ out) {
    __shared__ float2 Ps2[64][64];   // 32 KB, (p,p) duplicated pairs
    __shared__ float  Vs[64][64];    // 16 KB

    int b   = blockIdx.y;
    int i0  = blockIdx.x * 64;
    int tid = threadIdx.x;
    int rg  = tid >> 4;              // 16 row groups
    int jq  = tid & 15;              // stage1: j group; stage2: col group
    int r0  = rg * 4;                // rows r0..r0+3 (same for both stages)
    int c0  = jq * 4;

    // per-thread row data in registers
    float s1v[4];
#pragma unroll
    for (int k = 0; k < 4; k++) s1v[k] = g_s1[b * NN + i0 + r0 + k];

    const float*  s2b  = g_s2 + b * NN;
    const float4* wh_b = (const float4*)(g_Wh + (size_t)b * NN * FOUT);
    const int*    mptr = adj + (size_t)(b * NN + i0 + r0) * NN + 4 * jq;

    // V-tile load mapping: 1024 float4s / 256 threads = 4 each
    int vj[4], vc[4];
#pragma unroll
    for (int q = 0; q < 4; q++) {
        int idx = tid + q * 256;
        vj[q] = idx >> 4;
        vc[q] = idx & 15;
    }

    unsigned long long acc2[4][2] = {};              // 4 rows x 2 col-pairs
    float dsum[4] = {0.f, 0.f, 0.f, 0.f};

    // prefetch first tile's masks + s2
    int4   m[4];
#pragma unroll
    for (int k = 0; k < 4; k++) m[k] = *(const int4*)(mptr + (size_t)k * NN);
    float4 s2v = *(const float4*)(s2b + 4 * jq);

    const int NITER = NN / 64;
    for (int it = 0; it < NITER; ++it) {
        int j0 = it * 64;

        // issue V loads early (consumed at STS below)
        float4 vr[4];
#pragma unroll
        for (int q = 0; q < 4; q++)
            vr[q] = wh_b[(size_t)(j0 + vj[q]) * 16 + vc[q]];

        // ---- build P tile (duplicated pairs) + per-lane denom partials ----
#pragma unroll
        for (int k = 0; k < 4; k++) {
            float e0 = s1v[k] + s2v.x; e0 = e0 > 0.f ? e0 : 0.2f * e0;
            float e1 = s1v[k] + s2v.y; e1 = e1 > 0.f ? e1 : 0.2f * e1;
            float e2 = s1v[k] + s2v.z; e2 = e2 > 0.f ? e2 : 0.2f * e2;
            float e3 = s1v[k] + s2v.w; e3 = e3 > 0.f ? e3 : 0.2f * e3;
            float p0 = m[k].x ? fexp(e0) : 0.f;
            float p1 = m[k].y ? fexp(e1) : 0.f;
            float p2 = m[k].z ? fexp(e2) : 0.f;
            float p3 = m[k].w ? fexp(e3) : 0.f;
            *(float4*)&Ps2[r0 + k][4 * jq]     = make_float4(p0, p0, p1, p1);
            *(float4*)&Ps2[r0 + k][4 * jq + 2] = make_float4(p2, p2, p3, p3);
            dsum[k] += (p0 + p1) + (p2 + p3);
        }

        // ---- store V tile ----
#pragma unroll
        for (int q = 0; q < 4; q++)
            *(float4*)&Vs[vj[q]][vc[q] * 4] = vr[q];

        __syncthreads();

        // prefetch next tile's masks + s2 (overlaps with GEMM)
        if (it + 1 < NITER) {
            int jn = j0 + 64;
#pragma unroll
            for (int k = 0; k < 4; k++)
                m[k] = *(const int4*)(mptr + (size_t)k * NN + jn);
            s2v = *(const float4*)(s2b + jn + 4 * jq);
        }

        // ---- C += P_tile @ V_tile  (LDS.128 + FFMA2 only) ----
#pragma unroll 2
        for (int jj = 0; jj < 64; jj += 4) {
            ulonglong2 pA[4], pB[4];
#pragma unroll
            for (int k = 0; k < 4; k++) {
                pA[k] = *(const ulonglong2*)&Ps2[r0 + k][jj];       // (pp_j, pp_j+1)
                pB[k] = *(const ulonglong2*)&Ps2[r0 + k][jj + 2];   // (pp_j+2, pp_j+3)
            }
            ulonglong2 v0 = *(const ulonglong2*)&Vs[jj + 0][c0];
            ulonglong2 v1 = *(const ulonglong2*)&Vs[jj + 1][c0];
            ulonglong2 v2 = *(const ulonglong2*)&Vs[jj + 2][c0];
            ulonglong2 v3 = *(const ulonglong2*)&Vs[jj + 3][c0];
#pragma unroll
            for (int k = 0; k < 4; k++) {
                fma2(acc2[k][0], pA[k].x, v0.x); fma2(acc2[k][1], pA[k].x, v0.y);
                fma2(acc2[k][0], pA[k].y, v1.x); fma2(acc2[k][1], pA[k].y, v1.y);
                fma2(acc2[k][0], pB[k].x, v2.x); fma2(acc2[k][1], pB[k].x, v2.y);
                fma2(acc2[k][0], pB[k].y, v3.x); fma2(acc2[k][1], pB[k].y, v3.y);
            }
        }

        if (it + 1 < NITER) __syncthreads();
    }

    // ---- single denominator reduction (16-lane butterfly) ----
#pragma unroll
    for (int k = 0; k < 4; k++) {
#pragma unroll
        for (int ofs = 8; ofs >= 1; ofs >>= 1)
            dsum[k] += __shfl_xor_sync(0xffffffffu, dsum[k], ofs);
    }

    // ---- normalize + store ----
#pragma unroll
    for (int k = 0; k < 4; k++) {
        float inv = __fdividef(1.0f, dsum[k]);
        float lx, ly, hx, hy;
        asm("mov.b64 {%0, %1}, %2;" : "=f"(lx), "=f"(ly) : "l"(acc2[k][0]));
        asm("mov.b64 {%0, %1}, %2;" : "=f"(hx), "=f"(hy) : "l"(acc2[k][1]));
        *(float4*)&out[(size_t)(b * NN + i0 + r0 + k) * FOUT + c0] =
            make_float4(lx * inv, ly * inv, hx * inv, hy * inv);
    }
}

// ---------------------------------------------------------------------------
extern "C" void kernel_launch(void* const* d_in, const int* in_sizes, int n_in,
                              void* d_out, int out_size) {
    const float* h   = (const float*)d_in[0];
    const int*   adj = (const int*)d_in[1];
    const float* W   = (const float*)d_in[2];
    const float* a   = (const float*)d_in[3];
    float* out = (float*)d_out;

    wh_kernel<<<(B * NN) / 32, 256>>>(h, W, a);
    attn_kernel<<<dim3(NN / 64, B), 256>>>(adj, out);
}

// round 5
// speedup vs baseline: 1.4634x; 1.2825x over previous
#include <cuda_runtime.h>
#include <cuda_bf16.h>
#include <cstdint>

#define B    8
#define NN   2048
#define FIN  128
#define FOUT 64

// Scratch (no cudaMalloc allowed)
__device__ __align__(16) __nv_bfloat16 g_Vth[B * FOUT * NN];  // [b][n][j] hi
__device__ __align__(16) __nv_bfloat16 g_Vtl[B * FOUT * NN];  // [b][n][j] lo
__device__ __align__(16) float g_s1[B * NN];
__device__ __align__(16) float g_s2[B * NN];

// ---------------------------------------------------------------------------
// helpers
// ---------------------------------------------------------------------------
__device__ __forceinline__ float fexp(float x) {   // FMA-pipe exp, rel ~2e-6
    float z  = fmaf(x, 1.4426950408889634f, 12582912.0f);
    int   n  = __float_as_int(z) - 0x4B400000;
    float zf = z - 12582912.0f;
    float r  = fmaf(zf, -0.6931471805599453f, x);
    float p  =        1.3888889e-3f;
    p = fmaf(p, r,    8.3333333e-3f);
    p = fmaf(p, r,    4.1666668e-2f);
    p = fmaf(p, r,    1.6666667e-1f);
    p = fmaf(p, r,    5.0000000e-1f);
    p = fmaf(p, r,    1.0f);
    p = fmaf(p, r,    1.0f);
    return __int_as_float(__float_as_int(p) + (n << 23));
}

__device__ __forceinline__ uint32_t b2u(__nv_bfloat162 v) {
    return *reinterpret_cast<uint32_t*>(&v);
}

// split x into bf16 hi + bf16 lo (packed pairs)
__device__ __forceinline__ void split2(float x0, float x1,
                                       uint32_t& hi, uint32_t& lo) {
    __nv_bfloat162 h = __floats2bfloat162_rn(x0, x1);
    float r0 = x0 - __bfloat162float(h.x);
    float r1 = x1 - __bfloat162float(h.y);
    __nv_bfloat162 l = __floats2bfloat162_rn(r0, r1);
    hi = b2u(h);
    lo = b2u(l);
}

// m16n8k16 bf16 MMA, fp32 accumulate (baseline PTX feature, sm_80+)
__device__ __forceinline__ void mma16816(float* c, const uint32_t* a,
                                         uint32_t b0, uint32_t b1) {
    asm volatile(
        "mma.sync.aligned.m16n8k16.row.col.f32.bf16.bf16.f32 "
        "{%0,%1,%2,%3}, {%4,%5,%6,%7}, {%8,%9}, {%0,%1,%2,%3};"
        : "+f"(c[0]), "+f"(c[1]), "+f"(c[2]), "+f"(c[3])
        : "r"(a[0]), "r"(a[1]), "r"(a[2]), "r"(a[3]), "r"(b0), "r"(b1));
}

// ---------------------------------------------------------------------------
// Kernel 1: Wh = h @ W^T, fused s1/s2, emits transposed bf16 hi/lo V.
// 256 thr, 32 rows/CTA, grid 512.
// ---------------------------------------------------------------------------
__global__ __launch_bounds__(256) void wh_kernel(const float* __restrict__ h,
                                                 const float* __restrict__ W,
                                                 const float* __restrict__ a) {
    __shared__ float Wt[FIN][68];
    __shared__ float Tr[64][33];
    int tid = threadIdx.x;
    for (int idx = tid; idx < FOUT * FIN; idx += 256) {
        int o = idx >> 7, f = idx & 127;
        Wt[f][o] = W[idx];
    }
    __syncthreads();

    int row0 = blockIdx.x * 32;
    int rg = tid >> 4, cg = tid & 15;
    int r0 = row0 + rg * 2;
    int c0 = cg * 4;

    float acc[2][4] = {};
    const float* hp = h + (size_t)r0 * FIN;
    for (int f = 0; f < FIN; f += 4) {
        float4 wv0 = *(const float4*)&Wt[f + 0][c0];
        float4 wv1 = *(const float4*)&Wt[f + 1][c0];
        float4 wv2 = *(const float4*)&Wt[f + 2][c0];
        float4 wv3 = *(const float4*)&Wt[f + 3][c0];
#pragma unroll
        for (int k = 0; k < 2; k++) {
            float4 hv = __ldg((const float4*)(hp + k * FIN + f));
            acc[k][0] += hv.x * wv0.x + hv.y * wv1.x + hv.z * wv2.x + hv.w * wv3.x;
            acc[k][1] += hv.x * wv0.y + hv.y * wv1.y + hv.z * wv2.y + hv.w * wv3.y;
            acc[k][2] += hv.x * wv0.z + hv.y * wv1.z + hv.z * wv2.z + hv.w * wv3.z;
            acc[k][3] += hv.x * wv0.w + hv.y * wv1.w + hv.z * wv2.w + hv.w * wv3.w;
        }
    }

    float a1x = __ldg(&a[c0]),          a1y = __ldg(&a[c0 + 1]);
    float a1z = __ldg(&a[c0 + 2]),      a1w = __ldg(&a[c0 + 3]);
    float a2x = __ldg(&a[64 + c0]),     a2y = __ldg(&a[64 + c0 + 1]);
    float a2z = __ldg(&a[64 + c0 + 2]), a2w = __ldg(&a[64 + c0 + 3]);

#pragma unroll
    for (int k = 0; k < 2; k++) {
        float t1 = acc[k][0] * a1x + acc[k][1] * a1y + acc[k][2] * a1z + acc[k][3] * a1w;
        float t2 = acc[k][0] * a2x + acc[k][1] * a2y + acc[k][2] * a2z + acc[k][3] * a2w;
#pragma unroll
        for (int ofs = 8; ofs >= 1; ofs >>= 1) {
            t1 += __shfl_xor_sync(0xffffffffu, t1, ofs);
            t2 += __shfl_xor_sync(0xffffffffu, t2, ofs);
        }
        if (cg == 0) {
            g_s1[r0 + k] = t1;
            g_s2[r0 + k] = t2;
        }
#pragma unroll
        for (int q = 0; q < 4; q++) Tr[c0 + q][rg * 2 + k] = acc[k][q];
    }
    __syncthreads();

    // convert + split + store transposed bf16 (coalesced 16B per thread)
    {
        int c  = tid >> 2;
        int jl = (tid & 3) * 8;
        int bb = row0 >> 11;            // batch
        int jb = row0 & 2047;           // j offset within batch
        float v[8];
#pragma unroll
        for (int q = 0; q < 8; q++) v[q] = Tr[c][jl + q];
        uint32_t hu[4], lu[4];
#pragma unroll
        for (int q = 0; q < 4; q++)
            split2(v[2 * q], v[2 * q + 1], hu[q], lu[q]);
        size_t dst = ((size_t)bb * 64 + c) * NN + jb + jl;
        *(uint4*)(g_Vth + dst) = make_uint4(hu[0], hu[1], hu[2], hu[3]);
        *(uint4*)(g_Vtl + dst) = make_uint4(lu[0], lu[1], lu[2], lu[3]);
    }
}

// ---------------------------------------------------------------------------
// Kernel 2: fused masked-softmax attention; P@Wh via mma.sync (HMMA).
// Grid (16, 8): CTA = 128 rows, 8 warps x 16 rows. J streamed in 64-tiles.
// P built directly into A-fragments (never hits smem). V staged in smem,
// [n][k] layout, 144B row stride -> conflict-free B-fragment LDS.32.
// 3-MMA bf16 hi/lo compensation, fp32 accum. Denominators in registers.
// ---------------------------------------------------------------------------
__global__ __launch_bounds__(256, 1) void attn_kernel(const int* __restrict__ adj,
                                                      float* __restrict__ out) {
    __shared__ __nv_bfloat16 VsH[64][72];   // 9216 B
    __shared__ __nv_bfloat16 VsL[64][72];   // 9216 B

    int tid  = threadIdx.x;
    int w    = tid >> 5;
    int lane = tid & 31;
    int g    = lane >> 2;         // 0..7
    int t    = lane & 3;          // 0..3
    int b    = blockIdx.y;
    int i0   = blockIdx.x * 128;

    int rowg = i0 + w * 16 + g;   // lane's first row (within batch)
    const int*   mg  = adj + ((size_t)(b * NN + rowg)) * NN;
    const int*   mg8 = mg + (size_t)8 * NN;
    const float* s2b = g_s2 + b * NN;

    float f1g  = g_s1[b * NN + rowg];
    float f1g8 = g_s1[b * NN + rowg + 8];

    // V staging map: thread -> n row (tid>>2), 16-k chunk ((tid&3)*16)
    int vn = tid >> 2;
    int vk = (tid & 3) * 16;
    const __nv_bfloat16* vhp = g_Vth + ((size_t)b * 64 + vn) * NN;
    const __nv_bfloat16* vlp = g_Vtl + ((size_t)b * 64 + vn) * NN;

    float C[8][4] = {};           // 16x64 per warp
    float part_g = 0.f, part_g8 = 0.f;

    for (int it = 0; it < 32; ++it) {
        int j0 = it * 64;

        // ---- issue V gmem loads early ----
        uint4 h0 = *(const uint4*)(vhp + j0 + vk);
        uint4 h1 = *(const uint4*)(vhp + j0 + vk + 8);
        uint4 l0 = *(const uint4*)(vlp + j0 + vk);
        uint4 l1 = *(const uint4*)(vlp + j0 + vk + 8);

        // ---- stage 1: build P A-fragments in registers ----
        uint32_t aH[4][4], aL[4][4];
#pragma unroll
        for (int ks = 0; ks < 4; ks++) {
            int kk = j0 + ks * 16 + 2 * t;
            int2 m0 = *(const int2*)(mg  + kk);
            int2 m1 = *(const int2*)(mg  + kk + 8);
            int2 m2 = *(const int2*)(mg8 + kk);
            int2 m3 = *(const int2*)(mg8 + kk + 8);
            float2 sA = *(const float2*)(s2b + kk);
            float2 sB = *(const float2*)(s2b + kk + 8);

            float e, p00, p01, p02, p03, p10, p11, p12, p13;
            e = f1g  + sA.x; e = fmaxf(e, 0.2f * e); p00 = m0.x ? fexp(e) : 0.f;
            e = f1g  + sA.y; e = fmaxf(e, 0.2f * e); p01 = m0.y ? fexp(e) : 0.f;
            e = f1g  + sB.x; e = fmaxf(e, 0.2f * e); p02 = m1.x ? fexp(e) : 0.f;
            e = f1g  + sB.y; e = fmaxf(e, 0.2f * e); p03 = m1.y ? fexp(e) : 0.f;
            e = f1g8 + sA.x; e = fmaxf(e, 0.2f * e); p10 = m2.x ? fexp(e) : 0.f;
            e = f1g8 + sA.y; e = fmaxf(e, 0.2f * e); p11 = m2.y ? fexp(e) : 0.f;
            e = f1g8 + sB.x; e = fmaxf(e, 0.2f * e); p12 = m3.x ? fexp(e) : 0.f;
            e = f1g8 + sB.y; e = fmaxf(e, 0.2f * e); p13 = m3.y ? fexp(e) : 0.f;

            part_g  += (p00 + p01) + (p02 + p03);
            part_g8 += (p10 + p11) + (p12 + p13);

            split2(p00, p01, aH[ks][0], aL[ks][0]);   // row g,   k lo-pair
            split2(p10, p11, aH[ks][1], aL[ks][1]);   // row g+8, k lo-pair
            split2(p02, p03, aH[ks][2], aL[ks][2]);   // row g,   k hi-pair
            split2(p12, p13, aH[ks][3], aL[ks][3]);   // row g+8, k hi-pair
        }

        // ---- stage V tile into smem ----
        __syncthreads();                  // previous tile's B reads done
        *(uint4*)&VsH[vn][vk]     = h0;
        *(uint4*)&VsH[vn][vk + 8] = h1;
        *(uint4*)&VsL[vn][vk]     = l0;
        *(uint4*)&VsL[vn][vk + 8] = l1;
        __syncthreads();

        // ---- MMAs: Ph*Vh, Pl*Vh, Ph*Vl ----
#pragma unroll
        for (int ks = 0; ks < 4; ks++) {
            uint32_t bh[8][2], bl[8][2];
            int kb = ks * 16 + 2 * t;
#pragma unroll
            for (int ns = 0; ns < 8; ns++) {
                int n = 8 * ns + g;
                bh[ns][0] = *(const uint32_t*)&VsH[n][kb];
                bh[ns][1] = *(const uint32_t*)&VsH[n][kb + 8];
                bl[ns][0] = *(const uint32_t*)&VsL[n][kb];
                bl[ns][1] = *(const uint32_t*)&VsL[n][kb + 8];
            }
#pragma unroll
            for (int ns = 0; ns < 8; ns++)
                mma16816(C[ns], aH[ks], bh[ns][0], bh[ns][1]);
#pragma unroll
            for (int ns = 0; ns < 8; ns++)
                mma16816(C[ns], aL[ks], bh[ns][0], bh[ns][1]);
#pragma unroll
            for (int ns = 0; ns < 8; ns++)
                mma16816(C[ns], aH[ks], bl[ns][0], bl[ns][1]);
        }
    }

    // ---- denominators: butterfly over the 4 lanes sharing each row ----
    part_g  += __shfl_xor_sync(0xffffffffu, part_g, 1);
    part_g  += __shfl_xor_sync(0xffffffffu, part_g, 2);
    part_g8 += __shfl_xor_sync(0xffffffffu, part_g8, 1);
    part_g8 += __shfl_xor_sync(0xffffffffu, part_g8, 2);
    float invg  = __fdividef(1.0f, part_g);
    float invg8 = __fdividef(1.0f, part_g8);

    // ---- normalize + store (C layout: c0,c1 row g cols 2t,2t+1; c2,c3 row g+8)
    float* op = out + ((size_t)(b * NN + rowg)) * FOUT + 2 * t;
#pragma unroll
    for (int ns = 0; ns < 8; ns++) {
        *(float2*)(op + 8 * ns)       = make_float2(C[ns][0] * invg,  C[ns][1] * invg);
        *(float2*)(op + 8 * ns + 512) = make_float2(C[ns][2] * invg8, C[ns][3] * invg8);
    }
}

// ---------------------------------------------------------------------------
extern "C" void kernel_launch(void* const* d_in, const int* in_sizes, int n_in,
                              void* d_out, int out_size) {
    const float* h   = (const float*)d_in[0];
    const int*   adj = (const int*)d_in[1];
    const float* W   = (const float*)d_in[2];
    const float* a   = (const float*)d_in[3];
    float* out = (float*)d_out;

    wh_kernel<<<(B * NN) / 32, 256>>>(h, W, a);
    attn_kernel<<<dim3(NN / 128, B), 256>>>(adj, out);
}

// round 6
// speedup vs baseline: 1.6119x; 1.1014x over previous
#include <cuda_runtime.h>
#include <cuda_bf16.h>
#include <cstdint>

#define B    8
#define NN   2048
#define FIN  128
#define FOUT 64

// Scratch (no cudaMalloc allowed)
__device__ __align__(16) __nv_bfloat16 g_Vth[B * FOUT * NN];  // [b][n][j] hi
__device__ __align__(16) __nv_bfloat16 g_Vtl[B * FOUT * NN];  // [b][n][j] lo
__device__ __align__(16) float    g_s1[B * NN];
__device__ __align__(16) float    g_s2[B * NN];
__device__ __align__(16) uint32_t g_bm[B * NN * 64];          // 1 bit per adj

// ---------------------------------------------------------------------------
__device__ __forceinline__ float fexp(float x) {   // FMA-pipe exp, rel ~2e-6
    float z  = fmaf(x, 1.4426950408889634f, 12582912.0f);
    int   n  = __float_as_int(z) - 0x4B400000;
    float zf = z - 12582912.0f;
    float r  = fmaf(zf, -0.6931471805599453f, x);
    float p  =        1.3888889e-3f;
    p = fmaf(p, r,    8.3333333e-3f);
    p = fmaf(p, r,    4.1666668e-2f);
    p = fmaf(p, r,    1.6666667e-1f);
    p = fmaf(p, r,    5.0000000e-1f);
    p = fmaf(p, r,    1.0f);
    p = fmaf(p, r,    1.0f);
    return __int_as_float(__float_as_int(p) + (n << 23));
}

__device__ __forceinline__ uint32_t b2u(__nv_bfloat162 v) {
    return *reinterpret_cast<uint32_t*>(&v);
}
__device__ __forceinline__ void split2(float x0, float x1,
                                       uint32_t& hi, uint32_t& lo) {
    __nv_bfloat162 h = __floats2bfloat162_rn(x0, x1);
    float r0 = x0 - __bfloat162float(h.x);
    float r1 = x1 - __bfloat162float(h.y);
    __nv_bfloat162 l = __floats2bfloat162_rn(r0, r1);
    hi = b2u(h);
    lo = b2u(l);
}
__device__ __forceinline__ void mma16816(float* c, const uint32_t* a,
                                         uint32_t b0, uint32_t b1) {
    asm volatile(
        "mma.sync.aligned.m16n8k16.row.col.f32.bf16.bf16.f32 "
        "{%0,%1,%2,%3}, {%4,%5,%6,%7}, {%8,%9}, {%0,%1,%2,%3};"
        : "+f"(c[0]), "+f"(c[1]), "+f"(c[2]), "+f"(c[3])
        : "r"(a[0]), "r"(a[1]), "r"(a[2]), "r"(a[3]), "r"(b0), "r"(b1));
}

// ---------------------------------------------------------------------------
// Kernel 0: mask compaction. One warp per row; ballot packs 32 ints -> 1 word.
// ---------------------------------------------------------------------------
__global__ __launch_bounds__(256) void compact_kernel(const int* __restrict__ adj) {
    int warp = (blockIdx.x * 256 + threadIdx.x) >> 5;   // 0..16383 (row)
    int lane = threadIdx.x & 31;
    const int* rp = adj + (size_t)warp * NN + lane;
    uint32_t*  bp = g_bm + (size_t)warp * 64;
#pragma unroll 16
    for (int w = 0; w < 64; w++) {
        int v = __ldg(rp + w * 32);
        uint32_t word = __ballot_sync(0xffffffffu, v != 0);
        if (lane == 0) bp[w] = word;
    }
}

// ---------------------------------------------------------------------------
// Kernel 1: Wh = h @ W^T, fused s1/s2, emits transposed bf16 hi/lo V.
// ---------------------------------------------------------------------------
__global__ __launch_bounds__(256) void wh_kernel(const float* __restrict__ h,
                                                 const float* __restrict__ W,
                                                 const float* __restrict__ a) {
    __shared__ float Wt[FIN][68];
    __shared__ float Tr[64][33];
    int tid = threadIdx.x;
    for (int idx = tid; idx < FOUT * FIN; idx += 256) {
        int o = idx >> 7, f = idx & 127;
        Wt[f][o] = W[idx];
    }
    __syncthreads();

    int row0 = blockIdx.x * 32;
    int rg = tid >> 4, cg = tid & 15;
    int r0 = row0 + rg * 2;
    int c0 = cg * 4;

    float acc[2][4] = {};
    const float* hp = h + (size_t)r0 * FIN;
    for (int f = 0; f < FIN; f += 4) {
        float4 wv0 = *(const float4*)&Wt[f + 0][c0];
        float4 wv1 = *(const float4*)&Wt[f + 1][c0];
        float4 wv2 = *(const float4*)&Wt[f + 2][c0];
        float4 wv3 = *(const float4*)&Wt[f + 3][c0];
#pragma unroll
        for (int k = 0; k < 2; k++) {
            float4 hv = __ldg((const float4*)(hp + k * FIN + f));
            acc[k][0] += hv.x * wv0.x + hv.y * wv1.x + hv.z * wv2.x + hv.w * wv3.x;
            acc[k][1] += hv.x * wv0.y + hv.y * wv1.y + hv.z * wv2.y + hv.w * wv3.y;
            acc[k][2] += hv.x * wv0.z + hv.y * wv1.z + hv.z * wv2.z + hv.w * wv3.z;
            acc[k][3] += hv.x * wv0.w + hv.y * wv1.w + hv.z * wv2.w + hv.w * wv3.w;
        }
    }

    float a1x = __ldg(&a[c0]),          a1y = __ldg(&a[c0 + 1]);
    float a1z = __ldg(&a[c0 + 2]),      a1w = __ldg(&a[c0 + 3]);
    float a2x = __ldg(&a[64 + c0]),     a2y = __ldg(&a[64 + c0 + 1]);
    float a2z = __ldg(&a[64 + c0 + 2]), a2w = __ldg(&a[64 + c0 + 3]);

#pragma unroll
    for (int k = 0; k < 2; k++) {
        float t1 = acc[k][0] * a1x + acc[k][1] * a1y + acc[k][2] * a1z + acc[k][3] * a1w;
        float t2 = acc[k][0] * a2x + acc[k][1] * a2y + acc[k][2] * a2z + acc[k][3] * a2w;
#pragma unroll
        for (int ofs = 8; ofs >= 1; ofs >>= 1) {
            t1 += __shfl_xor_sync(0xffffffffu, t1, ofs);
            t2 += __shfl_xor_sync(0xffffffffu, t2, ofs);
        }
        if (cg == 0) {
            g_s1[r0 + k] = t1;
            g_s2[r0 + k] = t2;
        }
#pragma unroll
        for (int q = 0; q < 4; q++) Tr[c0 + q][rg * 2 + k] = acc[k][q];
    }
    __syncthreads();

    {
        int c  = tid >> 2;
        int jl = (tid & 3) * 8;
        int bb = row0 >> 11;
        int jb = row0 & 2047;
        float v[8];
#pragma unroll
        for (int q = 0; q < 8; q++) v[q] = Tr[c][jl + q];
        uint32_t hu[4], lu[4];
#pragma unroll
        for (int q = 0; q < 4; q++)
            split2(v[2 * q], v[2 * q + 1], hu[q], lu[q]);
        size_t dst = ((size_t)bb * 64 + c) * NN + jb + jl;
        *(uint4*)(g_Vth + dst) = make_uint4(hu[0], hu[1], hu[2], hu[3]);
        *(uint4*)(g_Vtl + dst) = make_uint4(lu[0], lu[1], lu[2], lu[3]);
    }
}

// ---------------------------------------------------------------------------
// Kernel 2: fused masked-softmax attention; P@Wh via mma.sync (HMMA).
// Grid (32, 8): CTA = 64 rows, 4 warps x 16 rows, 128 threads.
// Bitmask + s2 preloaded to smem (zero loop gmem loads besides V).
// V double-buffered in smem (reg-prefetched), ONE sync per iteration.
// 3-MMA bf16 hi/lo compensation, fp32 accum.
// ---------------------------------------------------------------------------
// dynamic smem layout (bytes):
#define SM_VH(buf) ((buf) * 9216)              // 2 x 64x72 bf16
#define SM_VL(buf) (18432 + (buf) * 9216)
#define SM_BM      36864                       // 64 rows x 66 words (padded)
#define SM_S2      53760                       // 2048 floats
#define SM_TOTAL   61952

__global__ __launch_bounds__(128, 2) void attn_kernel(float* __restrict__ out) {
    extern __shared__ __align__(16) char sm[];
    uint32_t* sBM = (uint32_t*)(sm + SM_BM);
    float*    sS2 = (float*)(sm + SM_S2);

    int tid  = threadIdx.x;
    int w    = tid >> 5;
    int lane = tid & 31;
    int g    = lane >> 2;
    int t    = lane & 3;
    int b    = blockIdx.y;
    int i0   = blockIdx.x * 64;

    // ---- preload bitmask (padded stride 66) + s2 into smem ----
    {
        const uint2* src = (const uint2*)(g_bm + ((size_t)(b * NN) + i0) * 64);
        for (int k = tid; k < 2048; k += 128) {
            uint2 v   = src[k];
            int   row = k >> 5;
            int   wd  = (k & 31) << 1;
            *(uint2*)&sBM[row * 66 + wd] = v;
        }
        const float4* s2src = (const float4*)(g_s2 + b * NN);
        float4*       s2dst = (float4*)sS2;
        for (int k = tid; k < 512; k += 128) s2dst[k] = s2src[k];
    }

    int   ilg  = w * 16 + g;
    float f1g  = g_s1[b * NN + i0 + ilg];
    float f1g8 = g_s1[b * NN + i0 + ilg + 8];

    // V prefetch map: 512 uint4 chunks per half; 4 per thread
    int vn[4], vkc[4];
#pragma unroll
    for (int k = 0; k < 4; k++) {
        int c = tid + k * 128;
        vn[k]  = c >> 3;
        vkc[k] = (c & 7) * 8;     // bf16 offset
    }
    const __nv_bfloat16* vhb = g_Vth + (size_t)b * 64 * NN;
    const __nv_bfloat16* vlb = g_Vtl + (size_t)b * 64 * NN;

    float C[8][4] = {};
    float part_g = 0.f, part_g8 = 0.f;

    // prefetch V tile 0
    uint4 vrH[4], vrL[4];
#pragma unroll
    for (int k = 0; k < 4; k++) {
        vrH[k] = *(const uint4*)(vhb + (size_t)vn[k] * NN + vkc[k]);
        vrL[k] = *(const uint4*)(vlb + (size_t)vn[k] * NN + vkc[k]);
    }
    __syncthreads();   // bm/s2 preload complete

    for (int it = 0; it < 32; ++it) {
        int buf = it & 1;
        int j0  = it * 64;

        // ---- stage 1: P A-fragments from smem bitmask + s2 ----
        uint32_t aH[4][4], aL[4][4];
        uint2 bmg  = *(const uint2*)&sBM[ilg * 66 + it * 2];
        uint2 bmg8 = *(const uint2*)&sBM[(ilg + 8) * 66 + it * 2];
#pragma unroll
        for (int ks = 0; ks < 4; ks++) {
            uint32_t wg  = (ks < 2) ? bmg.x  : bmg.y;
            uint32_t wg8 = (ks < 2) ? bmg8.x : bmg8.y;
            int base = ((ks & 1) << 4) + 2 * t;
            float2 sA = *(const float2*)&sS2[j0 + ks * 16 + 2 * t];
            float2 sB = *(const float2*)&sS2[j0 + ks * 16 + 2 * t + 8];

            float e, p00, p01, p02, p03, p10, p11, p12, p13;
            e = f1g  + sA.x; e = fmaxf(e, 0.2f * e); p00 = ((wg  >> base)       & 1) ? fexp(e) : 0.f;
            e = f1g  + sA.y; e = fmaxf(e, 0.2f * e); p01 = ((wg  >> (base + 1)) & 1) ? fexp(e) : 0.f;
            e = f1g  + sB.x; e = fmaxf(e, 0.2f * e); p02 = ((wg  >> (base + 8)) & 1) ? fexp(e) : 0.f;
            e = f1g  + sB.y; e = fmaxf(e, 0.2f * e); p03 = ((wg  >> (base + 9)) & 1) ? fexp(e) : 0.f;
            e = f1g8 + sA.x; e = fmaxf(e, 0.2f * e); p10 = ((wg8 >> base)       & 1) ? fexp(e) : 0.f;
            e = f1g8 + sA.y; e = fmaxf(e, 0.2f * e); p11 = ((wg8 >> (base + 1)) & 1) ? fexp(e) : 0.f;
            e = f1g8 + sB.x; e = fmaxf(e, 0.2f * e); p12 = ((wg8 >> (base + 8)) & 1) ? fexp(e) : 0.f;
            e = f1g8 + sB.y; e = fmaxf(e, 0.2f * e); p13 = ((wg8 >> (base + 9)) & 1) ? fexp(e) : 0.f;

            part_g  += (p00 + p01) + (p02 + p03);
            part_g8 += (p10 + p11) + (p12 + p13);

            split2(p00, p01, aH[ks][0], aL[ks][0]);
            split2(p10, p11, aH[ks][1], aL[ks][1]);
            split2(p02, p03, aH[ks][2], aL[ks][2]);
            split2(p12, p13, aH[ks][3], aL[ks][3]);
        }

        // ---- store prefetched V tile, then prefetch next ----
#pragma unroll
        for (int k = 0; k < 4; k++) {
            *(uint4*)(sm + SM_VH(buf) + vn[k] * 144 + vkc[k] * 2) = vrH[k];
            *(uint4*)(sm + SM_VL(buf) + vn[k] * 144 + vkc[k] * 2) = vrL[k];
        }
        if (it + 1 < 32) {
            int jn = j0 + 64;
#pragma unroll
            for (int k = 0; k < 4; k++) {
                vrH[k] = *(const uint4*)(vhb + (size_t)vn[k] * NN + jn + vkc[k]);
                vrL[k] = *(const uint4*)(vlb + (size_t)vn[k] * NN + jn + vkc[k]);
            }
        }
        __syncthreads();

        // ---- MMAs: Ph*Vh, Pl*Vh, Ph*Vl ----
        const char* vsh = sm + SM_VH(buf);
        const char* vsl = sm + SM_VL(buf);
#pragma unroll
        for (int ks = 0; ks < 4; ks++) {
            int kb = (ks * 16 + 2 * t) * 2;   // byte offset
            uint32_t bh[8][2], bl[8][2];
#pragma unroll
            for (int ns = 0; ns < 8; ns++) {
                int n = 8 * ns + g;
                bh[ns][0] = *(const uint32_t*)(vsh + n * 144 + kb);
                bh[ns][1] = *(const uint32_t*)(vsh + n * 144 + kb + 16);
                bl[ns][0] = *(const uint32_t*)(vsl + n * 144 + kb);
                bl[ns][1] = *(const uint32_t*)(vsl + n * 144 + kb + 16);
            }
#pragma unroll
            for (int ns = 0; ns < 8; ns++)
                mma16816(C[ns], aH[ks], bh[ns][0], bh[ns][1]);
#pragma unroll
            for (int ns = 0; ns < 8; ns++)
                mma16816(C[ns], aL[ks], bh[ns][0], bh[ns][1]);
#pragma unroll
            for (int ns = 0; ns < 8; ns++)
                mma16816(C[ns], aH[ks], bl[ns][0], bl[ns][1]);
        }
    }

    // ---- denominators ----
    part_g  += __shfl_xor_sync(0xffffffffu, part_g, 1);
    part_g  += __shfl_xor_sync(0xffffffffu, part_g, 2);
    part_g8 += __shfl_xor_sync(0xffffffffu, part_g8, 1);
    part_g8 += __shfl_xor_sync(0xffffffffu, part_g8, 2);
    float invg  = __fdividef(1.0f, part_g);
    float invg8 = __fdividef(1.0f, part_g8);

    // ---- normalize + store ----
    float* op = out + ((size_t)(b * NN + i0 + ilg)) * FOUT + 2 * t;
#pragma unroll
    for (int ns = 0; ns < 8; ns++) {
        *(float2*)(op + 8 * ns)       = make_float2(C[ns][0] * invg,  C[ns][1] * invg);
        *(float2*)(op + 8 * ns + 512) = make_float2(C[ns][2] * invg8, C[ns][3] * invg8);
    }
}

// ---------------------------------------------------------------------------
extern "C" void kernel_launch(void* const* d_in, const int* in_sizes, int n_in,
                              void* d_out, int out_size) {
    const float* h   = (const float*)d_in[0];
    const int*   adj = (const int*)d_in[1];
    const float* W   = (const float*)d_in[2];
    const float* a   = (const float*)d_in[3];
    float* out = (float*)d_out;

    static int smem_set = 0;
    if (!smem_set) {
        cudaFuncSetAttribute(attn_kernel,
                             cudaFuncAttributeMaxDynamicSharedMemorySize, SM_TOTAL);
        smem_set = 1;
    }

    compact_kernel<<<(B * NN) / 8, 256>>>(adj);
    wh_kernel<<<(B * NN) / 32, 256>>>(h, W, a);
    attn_kernel<<<dim3(NN / 64, B), 128, SM_TOTAL>>>(out);
}

// round 7
// speedup vs baseline: 1.9439x; 1.2060x over previous
#include <cuda_runtime.h>
#include <cuda_bf16.h>
#include <cstdint>

#define B    8
#define NN   2048
#define FIN  128
#define FOUT 64

// Scratch (no cudaMalloc allowed)
__device__ __align__(16) __nv_bfloat16 g_Vth[B * FOUT * NN];  // [b][n][j] hi
__device__ __align__(16) __nv_bfloat16 g_Vtl[B * FOUT * NN];  // [b][n][j] lo
__device__ __align__(16) float    g_s1[B * NN];
__device__ __align__(16) float    g_s2[B * NN];
__device__ __align__(16) uint32_t g_bm[B * NN * 64];          // interleaved bits
__device__ __align__(16) float    g_pC[2 * B * NN * FOUT];    // partial C
__device__ __align__(16) float    g_pd[2 * B * NN];           // partial denom

// ---------------------------------------------------------------------------
__device__ __forceinline__ float fexp(float x) {   // FMA-pipe exp, rel ~2e-6
    float z  = fmaf(x, 1.4426950408889634f, 12582912.0f);
    int   n  = __float_as_int(z) - 0x4B400000;
    float zf = z - 12582912.0f;
    float r  = fmaf(zf, -0.6931471805599453f, x);
    float p  =        1.3888889e-3f;
    p = fmaf(p, r,    8.3333333e-3f);
    p = fmaf(p, r,    4.1666668e-2f);
    p = fmaf(p, r,    1.6666667e-1f);
    p = fmaf(p, r,    5.0000000e-1f);
    p = fmaf(p, r,    1.0f);
    p = fmaf(p, r,    1.0f);
    return __int_as_float(__float_as_int(p) + (n << 23));
}

__device__ __forceinline__ uint32_t b2u(__nv_bfloat162 v) {
    return *reinterpret_cast<uint32_t*>(&v);
}
__device__ __forceinline__ void split2(float x0, float x1,
                                       uint32_t& hi, uint32_t& lo) {
    __nv_bfloat162 h = __floats2bfloat162_rn(x0, x1);
    float r0 = x0 - __bfloat162float(h.x);
    float r1 = x1 - __bfloat162float(h.y);
    hi = b2u(h);
    lo = b2u(__floats2bfloat162_rn(r0, r1));
}
// trunc-split: hi = trunc-to-bf16 (exact residual), PRMT pack, ALU-pipe heavy
__device__ __forceinline__ void splitT(float p0, float p1,
                                       uint32_t& hi, uint32_t& lo) {
    uint32_t i0 = __float_as_uint(p0), i1 = __float_as_uint(p1);
    float r0 = p0 - __uint_as_float(i0 & 0xffff0000u);
    float r1 = p1 - __uint_as_float(i1 & 0xffff0000u);
    asm("prmt.b32 %0, %1, %2, 0x7632;" : "=r"(hi) : "r"(i0), "r"(i1));
    lo = b2u(__floats2bfloat162_rn(r0, r1));
}
__device__ __forceinline__ void mma16816(float* c, const uint32_t* a,
                                         uint32_t b0, uint32_t b1) {
    asm volatile(
        "mma.sync.aligned.m16n8k16.row.col.f32.bf16.bf16.f32 "
        "{%0,%1,%2,%3}, {%4,%5,%6,%7}, {%8,%9}, {%0,%1,%2,%3};"
        : "+f"(c[0]), "+f"(c[1]), "+f"(c[2]), "+f"(c[3])
        : "r"(a[0]), "r"(a[1]), "r"(a[2]), "r"(a[3]), "r"(b0), "r"(b1));
}
__device__ __forceinline__ uint32_t smem_u32(const void* p) {
    uint32_t a;
    asm("{ .reg .u64 t; cvta.to.shared.u64 t, %1; cvt.u32.u64 %0, t; }"
        : "=r"(a) : "l"(p));
    return a;
}
#define CP16(dst, src) asm volatile("cp.async.cg.shared.global [%0], [%1], 16;" :: "r"(dst), "l"(src) : "memory")
#define CP_COMMIT()    asm volatile("cp.async.commit_group;" ::: "memory")
#define CP_WAIT0()     asm volatile("cp.async.wait_group 0;" ::: "memory")

// ---------------------------------------------------------------------------
// Kernel 0: mask compaction, int4 loads, interleaved ballot bit order.
// Bit for column j lives in word (j>>7)*4 + (j&3), bit index (j>>2)&31.
// ---------------------------------------------------------------------------
__global__ __launch_bounds__(256) void compact_kernel(const int* __restrict__ adj) {
    int warp = (blockIdx.x * 256 + threadIdx.x) >> 5;   // row 0..16383
    int lane = threadIdx.x & 31;
    const int4* rp = (const int4*)(adj + (size_t)warp * NN) + lane;
    uint4*      bp = (uint4*)(g_bm + (size_t)warp * 64);
#pragma unroll
    for (int r = 0; r < 16; r++) {
        int4 v = __ldg(rp + r * 32);
        uint32_t b0 = __ballot_sync(0xffffffffu, v.x != 0);
        uint32_t b1 = __ballot_sync(0xffffffffu, v.y != 0);
        uint32_t b2 = __ballot_sync(0xffffffffu, v.z != 0);
        uint32_t b3 = __ballot_sync(0xffffffffu, v.w != 0);
        if (lane == 0) bp[r] = make_uint4(b0, b1, b2, b3);
    }
}

// ---------------------------------------------------------------------------
// Kernel 1: Wh = h @ W^T, fused s1/s2, emits transposed bf16 hi/lo V.
// ---------------------------------------------------------------------------
__global__ __launch_bounds__(256) void wh_kernel(const float* __restrict__ h,
                                                 const float* __restrict__ W,
                                                 const float* __restrict__ a) {
    __shared__ float Wt[FIN][68];
    __shared__ float Tr[64][33];
    int tid = threadIdx.x;
    for (int idx = tid; idx < FOUT * FIN; idx += 256) {
        int o = idx >> 7, f = idx & 127;
        Wt[f][o] = W[idx];
    }
    __syncthreads();

    int row0 = blockIdx.x * 32;
    int rg = tid >> 4, cg = tid & 15;
    int r0 = row0 + rg * 2;
    int c0 = cg * 4;

    float acc[2][4] = {};
    const float* hp = h + (size_t)r0 * FIN;
    for (int f = 0; f < FIN; f += 4) {
        float4 wv0 = *(const float4*)&Wt[f + 0][c0];
        float4 wv1 = *(const float4*)&Wt[f + 1][c0];
        float4 wv2 = *(const float4*)&Wt[f + 2][c0];
        float4 wv3 = *(const float4*)&Wt[f + 3][c0];
#pragma unroll
        for (int k = 0; k < 2; k++) {
            float4 hv = __ldg((const float4*)(hp + k * FIN + f));
            acc[k][0] += hv.x * wv0.x + hv.y * wv1.x + hv.z * wv2.x + hv.w * wv3.x;
            acc[k][1] += hv.x * wv0.y + hv.y * wv1.y + hv.z * wv2.y + hv.w * wv3.y;
            acc[k][2] += hv.x * wv0.z + hv.y * wv1.z + hv.z * wv2.z + hv.w * wv3.z;
            acc[k][3] += hv.x * wv0.w + hv.y * wv1.w + hv.z * wv2.w + hv.w * wv3.w;
        }
    }

    float a1x = __ldg(&a[c0]),          a1y = __ldg(&a[c0 + 1]);
    float a1z = __ldg(&a[c0 + 2]),      a1w = __ldg(&a[c0 + 3]);
    float a2x = __ldg(&a[64 + c0]),     a2y = __ldg(&a[64 + c0 + 1]);
    float a2z = __ldg(&a[64 + c0 + 2]), a2w = __ldg(&a[64 + c0 + 3]);

#pragma unroll
    for (int k = 0; k < 2; k++) {
        float t1 = acc[k][0] * a1x + acc[k][1] * a1y + acc[k][2] * a1z + acc[k][3] * a1w;
        float t2 = acc[k][0] * a2x + acc[k][1] * a2y + acc[k][2] * a2z + acc[k][3] * a2w;
#pragma unroll
        for (int ofs = 8; ofs >= 1; ofs >>= 1) {
            t1 += __shfl_xor_sync(0xffffffffu, t1, ofs);
            t2 += __shfl_xor_sync(0xffffffffu, t2, ofs);
        }
        if (cg == 0) {
            g_s1[r0 + k] = t1;
            g_s2[r0 + k] = t2;
        }
#pragma unroll
        for (int q = 0; q < 4; q++) Tr[c0 + q][rg * 2 + k] = acc[k][q];
    }
    __syncthreads();

    {
        int c  = tid >> 2;
        int jl = (tid & 3) * 8;
        int bb = row0 >> 11;
        int jb = row0 & 2047;
        float v[8];
#pragma unroll
        for (int q = 0; q < 8; q++) v[q] = Tr[c][jl + q];
        uint32_t hu[4], lu[4];
#pragma unroll
        for (int q = 0; q < 4; q++)
            split2(v[2 * q], v[2 * q + 1], hu[q], lu[q]);
        size_t dst = ((size_t)bb * 64 + c) * NN + jb + jl;
        *(uint4*)(g_Vth + dst) = make_uint4(hu[0], hu[1], hu[2], hu[3]);
        *(uint4*)(g_Vtl + dst) = make_uint4(lu[0], lu[1], lu[2], lu[3]);
    }
}

// ---------------------------------------------------------------------------
// Kernel 2: attention partial. Grid (32, 8, 2): CTA = 64 i-rows x 1024 j-cols.
// 128 thr, 4 warps x 16 rows. V tiles via cp.async double buffer.
// Writes unnormalized partial C + partial denominators.
// ---------------------------------------------------------------------------
#define SM_VH(buf) ((buf) * 9216)              // 2 x 64x72 bf16
#define SM_VL(buf) (18432 + (buf) * 9216)
#define SM_BM      36864                       // 64 rows x 36 words
#define SM_S2      46080                       // 1024 floats
#define SM_TOTAL   50176

__global__ __launch_bounds__(128, 4) void attn_kernel() {
    extern __shared__ __align__(16) char sm[];
    uint32_t* sBM = (uint32_t*)(sm + SM_BM);
    float*    sS2 = (float*)(sm + SM_S2);
    uint32_t  sb  = smem_u32(sm);

    int tid  = threadIdx.x;
    int w    = tid >> 5;
    int lane = tid & 31;
    int g    = lane >> 2;
    int t    = lane & 3;
    int b    = blockIdx.y;
    int i0   = blockIdx.x * 64;
    int jh   = blockIdx.z;

    // ---- preload bitmask (36-word stride) + s2 half into smem ----
    {
        const uint32_t* bmsrc = g_bm + ((size_t)(b * NN) + i0) * 64 + jh * 32;
        for (int k = tid; k < 512; k += 128) {
            int r = k >> 3, w4 = (k & 7) * 4;
            uint4 v = *(const uint4*)(bmsrc + (size_t)r * 64 + w4);
            *(uint4*)&sBM[r * 36 + w4] = v;
        }
        const float4* s2src = (const float4*)(g_s2 + b * NN + jh * 1024);
        for (int k = tid; k < 256; k += 128) ((float4*)sS2)[k] = s2src[k];
    }

    int   ilg  = w * 16 + g;
    float f1g  = g_s1[b * NN + i0 + ilg];
    float f1g8 = g_s1[b * NN + i0 + ilg + 8];
    int   th   = t >> 1;

    // V cp.async map: 1024 16B-chunks per tile (hi+lo), 8 per thread
    int vn = tid >> 3;                 // 0..15 base row per thread (x4 sets)
    // simpler: chunk c = tid + q*128; row = c>>3, kcol = (c&7)*8
    const __nv_bfloat16* vhb = g_Vth + (size_t)b * 64 * NN + jh * 1024;
    const __nv_bfloat16* vlb = g_Vtl + (size_t)b * 64 * NN + jh * 1024;
    (void)vn;

    float C[8][4] = {};
    float part_g = 0.f, part_g8 = 0.f;

    // issue tile 0
#pragma unroll
    for (int q = 0; q < 4; q++) {
        int c = tid + q * 128;
        int r = c >> 3, kc = (c & 7) * 8;
        CP16(sb + SM_VH(0) + r * 144 + kc * 2, vhb + (size_t)r * NN + kc);
        CP16(sb + SM_VL(0) + r * 144 + kc * 2, vlb + (size_t)r * NN + kc);
    }
    CP_COMMIT();
    __syncthreads();    // bm/s2 visible

    uint4 bmg, bmg8;
    for (int it = 0; it < 16; ++it) {
        int buf = it & 1;
        int j0  = it * 64;

        if ((it & 1) == 0) {
            bmg  = *(const uint4*)&sBM[ilg * 36 + (it >> 1) * 4];
            bmg8 = *(const uint4*)&sBM[(ilg + 8) * 36 + (it >> 1) * 4];
        }
        uint32_t wAg  = (t & 1) ? bmg.z  : bmg.x;
        uint32_t wBg  = (t & 1) ? bmg.w  : bmg.y;
        uint32_t wAg8 = (t & 1) ? bmg8.z : bmg8.x;
        uint32_t wBg8 = (t & 1) ? bmg8.w : bmg8.y;
        int base16 = (it & 1) * 16;

        // ---- stage 1: P A-fragments ----
        uint32_t aH[4][4], aL[4][4];
#pragma unroll
        for (int ks = 0; ks < 4; ks++) {
            int b0 = base16 + 4 * ks + th;
            float2 sA = *(const float2*)&sS2[j0 + ks * 16 + 2 * t];
            float2 sB = *(const float2*)&sS2[j0 + ks * 16 + 2 * t + 8];

            float e, p00, p01, p02, p03, p10, p11, p12, p13;
            e = f1g  + sA.x; e = fmaxf(e, 0.2f * e); p00 = ((wAg  >> b0) & 1)       ? fexp(e) : 0.f;
            e = f1g  + sA.y; e = fmaxf(e, 0.2f * e); p01 = ((wBg  >> b0) & 1)       ? fexp(e) : 0.f;
            e = f1g  + sB.x; e = fmaxf(e, 0.2f * e); p02 = ((wAg  >> (b0 + 2)) & 1) ? fexp(e) : 0.f;
            e = f1g  + sB.y; e = fmaxf(e, 0.2f * e); p03 = ((wBg  >> (b0 + 2)) & 1) ? fexp(e) : 0.f;
            e = f1g8 + sA.x; e = fmaxf(e, 0.2f * e); p10 = ((wAg8 >> b0) & 1)       ? fexp(e) : 0.f;
            e = f1g8 + sA.y; e = fmaxf(e, 0.2f * e); p11 = ((wBg8 >> b0) & 1)       ? fexp(e) : 0.f;
            e = f1g8 + sB.x; e = fmaxf(e, 0.2f * e); p12 = ((wAg8 >> (b0 + 2)) & 1) ? fexp(e) : 0.f;
            e = f1g8 + sB.y; e = fmaxf(e, 0.2f * e); p13 = ((wBg8 >> (b0 + 2)) & 1) ? fexp(e) : 0.f;

            part_g  += (p00 + p01) + (p02 + p03);
            part_g8 += (p10 + p11) + (p12 + p13);

            splitT(p00, p01, aH[ks][0], aL[ks][0]);
            splitT(p10, p11, aH[ks][1], aL[ks][1]);
            splitT(p02, p03, aH[ks][2], aL[ks][2]);
            splitT(p12, p13, aH[ks][3], aL[ks][3]);
        }

        CP_WAIT0();            // tile it resident
        __syncthreads();

        // issue tile it+1 into the other buffer (prev reads finished above)
        if (it + 1 < 16) {
            int jn = j0 + 64;
#pragma unroll
            for (int q = 0; q < 4; q++) {
                int c = tid + q * 128;
                int r = c >> 3, kc = (c & 7) * 8;
                CP16(sb + SM_VH(1 - buf) + r * 144 + kc * 2,
                     vhb + (size_t)r * NN + jn + kc);
                CP16(sb + SM_VL(1 - buf) + r * 144 + kc * 2,
                     vlb + (size_t)r * NN + jn + kc);
            }
            CP_COMMIT();
        }

        // ---- MMAs: Ph*Vh, Pl*Vh, Ph*Vl ----
        const char* vsh = sm + SM_VH(buf);
        const char* vsl = sm + SM_VL(buf);
#pragma unroll
        for (int ks = 0; ks < 4; ks++) {
            int kb = (ks * 16 + 2 * t) * 2;
            uint32_t bh[8][2], bl[8][2];
#pragma unroll
            for (int ns = 0; ns < 8; ns++) {
                int n = 8 * ns + g;
                bh[ns][0] = *(const uint32_t*)(vsh + n * 144 + kb);
                bh[ns][1] = *(const uint32_t*)(vsh + n * 144 + kb + 16);
                bl[ns][0] = *(const uint32_t*)(vsl + n * 144 + kb);
                bl[ns][1] = *(const uint32_t*)(vsl + n * 144 + kb + 16);
            }
#pragma unroll
            for (int ns = 0; ns < 8; ns++)
                mma16816(C[ns], aH[ks], bh[ns][0], bh[ns][1]);
#pragma unroll
            for (int ns = 0; ns < 8; ns++)
                mma16816(C[ns], aL[ks], bh[ns][0], bh[ns][1]);
#pragma unroll
            for (int ns = 0; ns < 8; ns++)
                mma16816(C[ns], aH[ks], bl[ns][0], bl[ns][1]);
        }
    }

    // ---- partial denominators (4-lane quads) ----
    part_g  += __shfl_xor_sync(0xffffffffu, part_g, 1);
    part_g  += __shfl_xor_sync(0xffffffffu, part_g, 2);
    part_g8 += __shfl_xor_sync(0xffffffffu, part_g8, 1);
    part_g8 += __shfl_xor_sync(0xffffffffu, part_g8, 2);
    size_t growb = (size_t)b * NN + i0 + ilg;           // global row
    if (t == 0) {
        g_pd[(size_t)jh * (B * NN) + growb]     = part_g;
        g_pd[(size_t)jh * (B * NN) + growb + 8] = part_g8;
    }

    // ---- store partial C ----
    float* pc = g_pC + ((size_t)jh * (B * NN) + growb) * FOUT + 2 * t;
#pragma unroll
    for (int ns = 0; ns < 8; ns++) {
        *(float2*)(pc + 8 * ns)       = make_float2(C[ns][0], C[ns][1]);
        *(float2*)(pc + 8 * ns + 512) = make_float2(C[ns][2], C[ns][3]);
    }
}

// ---------------------------------------------------------------------------
// Kernel 3: combine halves + normalize.
// ---------------------------------------------------------------------------
__global__ __launch_bounds__(256) void combine_kernel(float* __restrict__ out) {
    int gid = blockIdx.x * 256 + threadIdx.x;      // 262144
    int row = gid >> 4;
    int q   = (gid & 15) * 4;
    float4 c0 = *(const float4*)(g_pC + (size_t)row * FOUT + q);
    float4 c1 = *(const float4*)(g_pC + (size_t)(B * NN + row) * FOUT + q);
    float inv = __fdividef(1.0f, g_pd[row] + g_pd[B * NN + row]);
    float4 o  = make_float4((c0.x + c1.x) * inv, (c0.y + c1.y) * inv,
                            (c0.z + c1.z) * inv, (c0.w + c1.w) * inv);
    *(float4*)(out + (size_t)row * FOUT + q) = o;
}

// ---------------------------------------------------------------------------
extern "C" void kernel_launch(void* const* d_in, const int* in_sizes, int n_in,
                              void* d_out, int out_size) {
    const float* h   = (const float*)d_in[0];
    const int*   adj = (const int*)d_in[1];
    const float* W   = (const float*)d_in[2];
    const float* a   = (const float*)d_in[3];
    float* out = (float*)d_out;

    static int smem_set = 0;
    if (!smem_set) {
        cudaFuncSetAttribute(attn_kernel,
                             cudaFuncAttributeMaxDynamicSharedMemorySize, SM_TOTAL);
        smem_set = 1;
    }

    compact_kernel<<<(B * NN) / 8, 256>>>(adj);
    wh_kernel<<<(B * NN) / 32, 256>>>(h, W, a);
    attn_kernel<<<dim3(NN / 64, B, 2), 128, SM_TOTAL>>>();
    combine_kernel<<<(B * NN * 16) / 256, 256>>>(out);
}

// round 8
// speedup vs baseline: 2.4425x; 1.2565x over previous
#include <cuda_runtime.h>
#include <cuda_bf16.h>
#include <cstdint>

#define B    8
#define NN   2048
#define FIN  128
#define FOUT 64

// Scratch (no cudaMalloc allowed)
__device__ __align__(16) __nv_bfloat16 g_Vth[B * FOUT * NN];  // [b][n][j] hi
__device__ __align__(16) __nv_bfloat16 g_Vtl[B * FOUT * NN];  // [b][n][j] lo
__device__ __align__(16) float    g_s1[B * NN];
__device__ __align__(16) float    g_s2[B * NN];
__device__ __align__(16) float2   g_e1[B * NN];               // (exp(s1), exp(.2 s1))
__device__ __align__(16) float2   g_e2[B * NN];               // (exp(s2), exp(.2 s2))
__device__ __align__(16) uint32_t g_bm[B * NN * 64];          // interleaved bits
__device__ __align__(16) float    g_pC[2 * B * NN * FOUT];    // partial C
__device__ __align__(16) float    g_pd[2 * B * NN];           // partial denom

// ---------------------------------------------------------------------------
__device__ __forceinline__ float fexp(float x) {   // FMA-pipe exp, rel ~2e-6
    float z  = fmaf(x, 1.4426950408889634f, 12582912.0f);
    int   n  = __float_as_int(z) - 0x4B400000;
    float zf = z - 12582912.0f;
    float r  = fmaf(zf, -0.6931471805599453f, x);
    float p  =        1.3888889e-3f;
    p = fmaf(p, r,    8.3333333e-3f);
    p = fmaf(p, r,    4.1666668e-2f);
    p = fmaf(p, r,    1.6666667e-1f);
    p = fmaf(p, r,    5.0000000e-1f);
    p = fmaf(p, r,    1.0f);
    p = fmaf(p, r,    1.0f);
    return __int_as_float(__float_as_int(p) + (n << 23));
}

__device__ __forceinline__ uint32_t b2u(__nv_bfloat162 v) {
    return *reinterpret_cast<uint32_t*>(&v);
}
__device__ __forceinline__ void split2(float x0, float x1,
                                       uint32_t& hi, uint32_t& lo) {
    __nv_bfloat162 h = __floats2bfloat162_rn(x0, x1);
    float r0 = x0 - __bfloat162float(h.x);
    float r1 = x1 - __bfloat162float(h.y);
    hi = b2u(h);
    lo = b2u(__floats2bfloat162_rn(r0, r1));
}
// trunc-split (exact residual), PRMT pack, ALU-pipe heavy
__device__ __forceinline__ void splitT(float p0, float p1,
                                       uint32_t& hi, uint32_t& lo) {
    uint32_t i0 = __float_as_uint(p0), i1 = __float_as_uint(p1);
    float r0 = p0 - __uint_as_float(i0 & 0xffff0000u);
    float r1 = p1 - __uint_as_float(i1 & 0xffff0000u);
    asm("prmt.b32 %0, %1, %2, 0x7632;" : "=r"(hi) : "r"(i0), "r"(i1));
    lo = b2u(__floats2bfloat162_rn(r0, r1));
}
// factorized masked lrelu-exp
__device__ __forceinline__ float pcalc(float s1, float e1p, float e1n,
                                       float s2, float e2p, float e2n,
                                       uint32_t w, int bit) {
    float t = s1 + s2;
    float p = (t > 0.f) ? e1p * e2p : e1n * e2n;
    return ((w >> bit) & 1u) ? p : 0.f;
}
__device__ __forceinline__ void mma16816(float* c, const uint32_t* a,
                                         uint32_t b0, uint32_t b1) {
    asm volatile(
        "mma.sync.aligned.m16n8k16.row.col.f32.bf16.bf16.f32 "
        "{%0,%1,%2,%3}, {%4,%5,%6,%7}, {%8,%9}, {%0,%1,%2,%3};"
        : "+f"(c[0]), "+f"(c[1]), "+f"(c[2]), "+f"(c[3])
        : "r"(a[0]), "r"(a[1]), "r"(a[2]), "r"(a[3]), "r"(b0), "r"(b1));
}
__device__ __forceinline__ void ldsm4(uint32_t& r0, uint32_t& r1,
                                      uint32_t& r2, uint32_t& r3, uint32_t a) {
    asm volatile("ldmatrix.sync.aligned.m8n8.x4.shared.b16 {%0,%1,%2,%3}, [%4];"
                 : "=r"(r0), "=r"(r1), "=r"(r2), "=r"(r3) : "r"(a));
}
__device__ __forceinline__ uint32_t smem_u32(const void* p) {
    uint32_t a;
    asm("{ .reg .u64 t; cvta.to.shared.u64 t, %1; cvt.u32.u64 %0, t; }"
        : "=r"(a) : "l"(p));
    return a;
}
#define CP16(dst, src) asm volatile("cp.async.cg.shared.global [%0], [%1], 16;" :: "r"(dst), "l"(src) : "memory")
#define CP_COMMIT()    asm volatile("cp.async.commit_group;" ::: "memory")
#define CP_WAIT0()     asm volatile("cp.async.wait_group 0;" ::: "memory")

// ---------------------------------------------------------------------------
// Kernel 0: mask compaction (int4 loads, interleaved ballot bit order).
// Bit for column j: word (j>>7)*4 + (j&3), bit (j>>2)&31.
// ---------------------------------------------------------------------------
__global__ __launch_bounds__(256) void compact_kernel(const int* __restrict__ adj) {
    int warp = (blockIdx.x * 256 + threadIdx.x) >> 5;
    int lane = threadIdx.x & 31;
    const int4* rp = (const int4*)(adj + (size_t)warp * NN) + lane;
    uint4*      bp = (uint4*)(g_bm + (size_t)warp * 64);
#pragma unroll
    for (int r = 0; r < 16; r++) {
        int4 v = __ldg(rp + r * 32);
        uint32_t b0 = __ballot_sync(0xffffffffu, v.x != 0);
        uint32_t b1 = __ballot_sync(0xffffffffu, v.y != 0);
        uint32_t b2 = __ballot_sync(0xffffffffu, v.z != 0);
        uint32_t b3 = __ballot_sync(0xffffffffu, v.w != 0);
        if (lane == 0) bp[r] = make_uint4(b0, b1, b2, b3);
    }
}

// ---------------------------------------------------------------------------
// Kernel 1: Wh = h @ W^T, fused s1/s2 (+ factorized exp tables), emits
// transposed bf16 hi/lo V. h loads double-buffered in registers.
// ---------------------------------------------------------------------------
__global__ __launch_bounds__(256) void wh_kernel(const float* __restrict__ h,
                                                 const float* __restrict__ W,
                                                 const float* __restrict__ a) {
    __shared__ float Wt[FIN][68];
    __shared__ float Tr[64][33];
    int tid = threadIdx.x;
    for (int idx = tid; idx < FOUT * FIN; idx += 256) {
        int o = idx >> 7, f = idx & 127;
        Wt[f][o] = W[idx];
    }
    __syncthreads();

    int row0 = blockIdx.x * 32;
    int rg = tid >> 4, cg = tid & 15;
    int r0 = row0 + rg * 2;
    int c0 = cg * 4;

    float acc[2][4] = {};
    const float* hp = h + (size_t)r0 * FIN;
    float4 hc0 = __ldg((const float4*)hp);
    float4 hc1 = __ldg((const float4*)(hp + FIN));
#pragma unroll 4
    for (int f = 0; f < FIN; f += 4) {
        float4 hn0, hn1;
        if (f + 4 < FIN) {
            hn0 = __ldg((const float4*)(hp + f + 4));
            hn1 = __ldg((const float4*)(hp + FIN + f + 4));
        }
        float4 wv0 = *(const float4*)&Wt[f + 0][c0];
        float4 wv1 = *(const float4*)&Wt[f + 1][c0];
        float4 wv2 = *(const float4*)&Wt[f + 2][c0];
        float4 wv3 = *(const float4*)&Wt[f + 3][c0];
        acc[0][0] += hc0.x * wv0.x + hc0.y * wv1.x + hc0.z * wv2.x + hc0.w * wv3.x;
        acc[0][1] += hc0.x * wv0.y + hc0.y * wv1.y + hc0.z * wv2.y + hc0.w * wv3.y;
        acc[0][2] += hc0.x * wv0.z + hc0.y * wv1.z + hc0.z * wv2.z + hc0.w * wv3.z;
        acc[0][3] += hc0.x * wv0.w + hc0.y * wv1.w + hc0.z * wv2.w + hc0.w * wv3.w;
        acc[1][0] += hc1.x * wv0.x + hc1.y * wv1.x + hc1.z * wv2.x + hc1.w * wv3.x;
        acc[1][1] += hc1.x * wv0.y + hc1.y * wv1.y + hc1.z * wv2.y + hc1.w * wv3.y;
        acc[1][2] += hc1.x * wv0.z + hc1.y * wv1.z + hc1.z * wv2.z + hc1.w * wv3.z;
        acc[1][3] += hc1.x * wv0.w + hc1.y * wv1.w + hc1.z * wv2.w + hc1.w * wv3.w;
        hc0 = hn0; hc1 = hn1;
    }

    float a1x = __ldg(&a[c0]),          a1y = __ldg(&a[c0 + 1]);
    float a1z = __ldg(&a[c0 + 2]),      a1w = __ldg(&a[c0 + 3]);
    float a2x = __ldg(&a[64 + c0]),     a2y = __ldg(&a[64 + c0 + 1]);
    float a2z = __ldg(&a[64 + c0 + 2]), a2w = __ldg(&a[64 + c0 + 3]);

#pragma unroll
    for (int k = 0; k < 2; k++) {
        float t1 = acc[k][0] * a1x + acc[k][1] * a1y + acc[k][2] * a1z + acc[k][3] * a1w;
        float t2 = acc[k][0] * a2x + acc[k][1] * a2y + acc[k][2] * a2z + acc[k][3] * a2w;
#pragma unroll
        for (int ofs = 8; ofs >= 1; ofs >>= 1) {
            t1 += __shfl_xor_sync(0xffffffffu, t1, ofs);
            t2 += __shfl_xor_sync(0xffffffffu, t2, ofs);
        }
        if (cg == 0) {
            g_s1[r0 + k] = t1;
            g_s2[r0 + k] = t2;
            g_e1[r0 + k] = make_float2(fexp(t1), fexp(0.2f * t1));
            g_e2[r0 + k] = make_float2(fexp(t2), fexp(0.2f * t2));
        }
#pragma unroll
        for (int q = 0; q < 4; q++) Tr[c0 + q][rg * 2 + k] = acc[k][q];
    }
    __syncthreads();

    {
        int c  = tid >> 2;
        int jl = (tid & 3) * 8;
        int bb = row0 >> 11;
        int jb = row0 & 2047;
        float v[8];
#pragma unroll
        for (int q = 0; q < 8; q++) v[q] = Tr[c][jl + q];
        uint32_t hu[4], lu[4];
#pragma unroll
        for (int q = 0; q < 4; q++)
            split2(v[2 * q], v[2 * q + 1], hu[q], lu[q]);
        size_t dst = ((size_t)bb * 64 + c) * NN + jb + jl;
        *(uint4*)(g_Vth + dst) = make_uint4(hu[0], hu[1], hu[2], hu[3]);
        *(uint4*)(g_Vtl + dst) = make_uint4(lu[0], lu[1], lu[2], lu[3]);
    }
}

// ---------------------------------------------------------------------------
// Kernel 2: attention partial. Grid (32, 8, 2): CTA = 64 i x 1024 j.
// Factorized exp (no exps in-loop), ldmatrix B fragments, cp.async V,
// bitmask register-prefetched from gmem. 3-MMA bf16 hi/lo compensation.
// ---------------------------------------------------------------------------
#define SM_VH(buf) ((buf) * 9216)              // 2 x 64x72 bf16
#define SM_VL(buf) (18432 + (buf) * 9216)
#define SM_E2      36864                       // float2[1024]
#define SM_S2      45056                       // float[1024]
#define SM_TOTAL   49152

__global__ __launch_bounds__(128, 4) void attn_kernel() {
    extern __shared__ __align__(16) char sm[];
    float* sE2 = (float*)(sm + SM_E2);
    float* sS2 = (float*)(sm + SM_S2);
    uint32_t sb = smem_u32(sm);

    int tid  = threadIdx.x;
    int w    = tid >> 5;
    int lane = tid & 31;
    int g    = lane >> 2;
    int t    = lane & 3;
    int th   = t >> 1;
    int b    = blockIdx.y;
    int i0   = blockIdx.x * 64;
    int jh   = blockIdx.z;

    // ---- preload e2/s2 tables into smem ----
    {
        const float4* e2src = (const float4*)(g_e2 + b * NN + jh * 1024);
        float4*       e2dst = (float4*)sE2;
#pragma unroll
        for (int k = 0; k < 4; k++) e2dst[tid + k * 128] = e2src[tid + k * 128];
        const float4* s2src = (const float4*)(g_s2 + b * NN + jh * 1024);
        float4*       s2dst = (float4*)sS2;
#pragma unroll
        for (int k = 0; k < 2; k++) s2dst[tid + k * 128] = s2src[tid + k * 128];
    }

    int    ilg = w * 16 + g;
    float  s1g  = g_s1[b * NN + i0 + ilg];
    float  s1g8 = g_s1[b * NN + i0 + ilg + 8];
    float2 e1g  = g_e1[b * NN + i0 + ilg];
    float2 e1g8 = g_e1[b * NN + i0 + ilg + 8];

    // bitmask gmem pointers + first group prefetch
    const uint4* bmp  = (const uint4*)(g_bm + (size_t)(b * NN + i0 + ilg) * 64 + jh * 32);
    const uint4* bmp8 = (const uint4*)(g_bm + (size_t)(b * NN + i0 + ilg + 8) * 64 + jh * 32);
    uint4 curg  = __ldg(bmp);
    uint4 curg8 = __ldg(bmp8);
    uint4 nxtg  = curg, nxtg8 = curg8;

    // V source pointers
    const __nv_bfloat16* vhb = g_Vth + (size_t)b * 64 * NN + jh * 1024;
    const __nv_bfloat16* vlb = g_Vtl + (size_t)b * 64 * NN + jh * 1024;

    // ldmatrix lane-constant offset
    uint32_t lsm_off = (((lane >> 4) & 1) * 8 + (lane & 7)) * 144
                     + ((lane >> 3) & 1) * 16;

    float C[8][4] = {};
    float part_g = 0.f, part_g8 = 0.f;

    // issue V tile 0
#pragma unroll
    for (int q = 0; q < 4; q++) {
        int c = tid + q * 128;
        int r = c >> 3, kc = (c & 7) * 8;
        CP16(sb + SM_VH(0) + r * 144 + kc * 2, vhb + (size_t)r * NN + kc);
        CP16(sb + SM_VL(0) + r * 144 + kc * 2, vlb + (size_t)r * NN + kc);
    }
    CP_COMMIT();
    __syncthreads();   // e2/s2 visible

    uint32_t wAg = 0, wBg = 0, wAg8 = 0, wBg8 = 0;

    for (int it = 0; it < 16; ++it) {
        int buf = it & 1;
        int j0  = it * 64;

        if ((it & 1) == 0) {
            if (it > 0) { curg = nxtg; curg8 = nxtg8; }
            wAg  = (t & 1) ? curg.z  : curg.x;
            wBg  = (t & 1) ? curg.w  : curg.y;
            wAg8 = (t & 1) ? curg8.z : curg8.x;
            wBg8 = (t & 1) ? curg8.w : curg8.y;
        }
        int base16 = (it & 1) * 16;

        // ---- stage 1: P A-fragments (factorized exp) ----
        uint32_t aH[4][4], aL[4][4];
#pragma unroll
        for (int ks = 0; ks < 4; ks++) {
            int jb = j0 + ks * 16 + 2 * t;
            int b0 = base16 + 4 * ks + th;
            float2 sA = *(const float2*)&sS2[jb - j0 + j0];        // s2[jb]
            float2 sB = *(const float2*)&sS2[jb + 8];
            float4 eA = *(const float4*)&sE2[2 * jb];
            float4 eB = *(const float4*)&sE2[2 * (jb + 8)];

            float p00 = pcalc(s1g,  e1g.x,  e1g.y,  sA.x, eA.x, eA.y, wAg,  b0);
            float p01 = pcalc(s1g,  e1g.x,  e1g.y,  sA.y, eA.z, eA.w, wBg,  b0);
            float p02 = pcalc(s1g,  e1g.x,  e1g.y,  sB.x, eB.x, eB.y, wAg,  b0 + 2);
            float p03 = pcalc(s1g,  e1g.x,  e1g.y,  sB.y, eB.z, eB.w, wBg,  b0 + 2);
            float p10 = pcalc(s1g8, e1g8.x, e1g8.y, sA.x, eA.x, eA.y, wAg8, b0);
            float p11 = pcalc(s1g8, e1g8.x, e1g8.y, sA.y, eA.z, eA.w, wBg8, b0);
            float p12 = pcalc(s1g8, e1g8.x, e1g8.y, sB.x, eB.x, eB.y, wAg8, b0 + 2);
            float p13 = pcalc(s1g8, e1g8.x, e1g8.y, sB.y, eB.z, eB.w, wBg8, b0 + 2);

            part_g  += (p00 + p01) + (p02 + p03);
            part_g8 += (p10 + p11) + (p12 + p13);

            splitT(p00, p01, aH[ks][0], aL[ks][0]);
            splitT(p10, p11, aH[ks][1], aL[ks][1]);
            splitT(p02, p03, aH[ks][2], aL[ks][2]);
            splitT(p12, p13, aH[ks][3], aL[ks][3]);
        }

        CP_WAIT0();
        __syncthreads();

        // issue next V tile
        if (it + 1 < 16) {
            int jn = j0 + 64;
#pragma unroll
            for (int q = 0; q < 4; q++) {
                int c = tid + q * 128;
                int r = c >> 3, kc = (c & 7) * 8;
                CP16(sb + SM_VH(1 - buf) + r * 144 + kc * 2,
                     vhb + (size_t)r * NN + jn + kc);
                CP16(sb + SM_VL(1 - buf) + r * 144 + kc * 2,
                     vlb + (size_t)r * NN + jn + kc);
            }
            CP_COMMIT();
        }
        // prefetch next bitmask group
        if ((it & 1) == 0 && it + 2 < 16) {
            int grp = (it >> 1) + 1;
            nxtg  = __ldg(bmp + grp);
            nxtg8 = __ldg(bmp8 + grp);
        }

        // ---- MMAs via ldmatrix: Ph*Vh, Pl*Vh, Ph*Vl ----
        uint32_t baseH = sb + SM_VH(buf) + lsm_off;
        uint32_t baseL = sb + SM_VL(buf) + lsm_off;
#pragma unroll
        for (int ks = 0; ks < 4; ks++) {
#pragma unroll
            for (int p = 0; p < 4; p++) {
                uint32_t bh0, bh1, bh2, bh3, bl0, bl1, bl2, bl3;
                ldsm4(bh0, bh1, bh2, bh3, baseH + p * 2304 + ks * 32);
                ldsm4(bl0, bl1, bl2, bl3, baseL + p * 2304 + ks * 32);
                mma16816(C[2 * p],     aH[ks], bh0, bh1);
                mma16816(C[2 * p + 1], aH[ks], bh2, bh3);
                mma16816(C[2 * p],     aL[ks], bh0, bh1);
                mma16816(C[2 * p + 1], aL[ks], bh2, bh3);
                mma16816(C[2 * p],     aH[ks], bl0, bl1);
                mma16816(C[2 * p + 1], aH[ks], bl2, bl3);
            }
        }
    }

    // ---- partial denominators (4-lane quads) ----
    part_g  += __shfl_xor_sync(0xffffffffu, part_g, 1);
    part_g  += __shfl_xor_sync(0xffffffffu, part_g, 2);
    part_g8 += __shfl_xor_sync(0xffffffffu, part_g8, 1);
    part_g8 += __shfl_xor_sync(0xffffffffu, part_g8, 2);
    size_t growb = (size_t)b * NN + i0 + ilg;
    if (t == 0) {
        g_pd[(size_t)jh * (B * NN) + growb]     = part_g;
        g_pd[(size_t)jh * (B * NN) + growb + 8] = part_g8;
    }

    // ---- store partial C ----
    float* pc = g_pC + ((size_t)jh * (B * NN) + growb) * FOUT + 2 * t;
#pragma unroll
    for (int ns = 0; ns < 8; ns++) {
        *(float2*)(pc + 8 * ns)       = make_float2(C[ns][0], C[ns][1]);
        *(float2*)(pc + 8 * ns + 512) = make_float2(C[ns][2], C[ns][3]);
    }
}

// ---------------------------------------------------------------------------
// Kernel 3: combine halves + normalize.
// ---------------------------------------------------------------------------
__global__ __launch_bounds__(256) void combine_kernel(float* __restrict__ out) {
    int gid = blockIdx.x * 256 + threadIdx.x;
    int row = gid >> 4;
    int q   = (gid & 15) * 4;
    float4 c0 = *(const float4*)(g_pC + (size_t)row * FOUT + q);
    float4 c1 = *(const float4*)(g_pC + (size_t)(B * NN + row) * FOUT + q);
    float inv = __fdividef(1.0f, g_pd[row] + g_pd[B * NN + row]);
    float4 o  = make_float4((c0.x + c1.x) * inv, (c0.y + c1.y) * inv,
                            (c0.z + c1.z) * inv, (c0.w + c1.w) * inv);
    *(float4*)(out + (size_t)row * FOUT + q) = o;
}

// ---------------------------------------------------------------------------
extern "C" void kernel_launch(void* const* d_in, const int* in_sizes, int n_in,
                              void* d_out, int out_size) {
    const float* h   = (const float*)d_in[0];
    const int*   adj = (const int*)d_in[1];
    const float* W   = (const float*)d_in[2];
    const float* a   = (const float*)d_in[3];
    float* out = (float*)d_out;

    static int smem_set = 0;
    if (!smem_set) {
        cudaFuncSetAttribute(attn_kernel,
                             cudaFuncAttributeMaxDynamicSharedMemorySize, SM_TOTAL);
        smem_set = 1;
    }

    compact_kernel<<<(B * NN) / 8, 256>>>(adj);
    wh_kernel<<<(B * NN) / 32, 256>>>(h, W, a);
    attn_kernel<<<dim3(NN / 64, B, 2), 128, SM_TOTAL>>>();
    combine_kernel<<<(B * NN * 16) / 256, 256>>>(out);
}

// round 9
// speedup vs baseline: 2.6115x; 1.0692x over previous
#include <cuda_runtime.h>
#include <cuda_bf16.h>
#include <cstdint>

#define B    8
#define NN   2048
#define FIN  128
#define FOUT 64

// Scratch (no cudaMalloc allowed)
__device__ __align__(16) __nv_bfloat16 g_Vth[B * FOUT * NN];  // [b][n][j] hi
__device__ __align__(16) __nv_bfloat16 g_Vtl[B * FOUT * NN];  // [b][n][j] lo
__device__ __align__(16) float    g_s1[B * NN];
__device__ __align__(16) float    g_s2[B * NN];
__device__ __align__(16) float2   g_e1[B * NN];               // (exp(s1), exp(.2 s1))
__device__ __align__(16) float2   g_e2[B * NN];               // (exp(s2), exp(.2 s2))
__device__ __align__(16) uint32_t g_bm[B * NN * 64];          // interleaved bits
__device__ __align__(16) float    g_pC[2 * B * NN * FOUT];    // partial C
__device__ __align__(16) float    g_pd[2 * B * NN];           // partial denom

// ---------------------------------------------------------------------------
__device__ __forceinline__ float fexp(float x) {   // FMA-pipe exp, rel ~2e-6
    float z  = fmaf(x, 1.4426950408889634f, 12582912.0f);
    int   n  = __float_as_int(z) - 0x4B400000;
    float zf = z - 12582912.0f;
    float r  = fmaf(zf, -0.6931471805599453f, x);
    float p  =        1.3888889e-3f;
    p = fmaf(p, r,    8.3333333e-3f);
    p = fmaf(p, r,    4.1666668e-2f);
    p = fmaf(p, r,    1.6666667e-1f);
    p = fmaf(p, r,    5.0000000e-1f);
    p = fmaf(p, r,    1.0f);
    p = fmaf(p, r,    1.0f);
    return __int_as_float(__float_as_int(p) + (n << 23));
}

__device__ __forceinline__ uint32_t b2u(__nv_bfloat162 v) {
    return *reinterpret_cast<uint32_t*>(&v);
}
__device__ __forceinline__ void split2(float x0, float x1,
                                       uint32_t& hi, uint32_t& lo) {
    __nv_bfloat162 h = __floats2bfloat162_rn(x0, x1);
    float r0 = x0 - __bfloat162float(h.x);
    float r1 = x1 - __bfloat162float(h.y);
    hi = b2u(h);
    lo = b2u(__floats2bfloat162_rn(r0, r1));
}
// trunc-split (exact residual), PRMT pack, ALU-pipe heavy
__device__ __forceinline__ void splitT(float p0, float p1,
                                       uint32_t& hi, uint32_t& lo) {
    uint32_t i0 = __float_as_uint(p0), i1 = __float_as_uint(p1);
    float r0 = p0 - __uint_as_float(i0 & 0xffff0000u);
    float r1 = p1 - __uint_as_float(i1 & 0xffff0000u);
    asm("prmt.b32 %0, %1, %2, 0x7632;" : "=r"(hi) : "r"(i0), "r"(i1));
    lo = b2u(__floats2bfloat162_rn(r0, r1));
}
// factorized masked lrelu-exp
__device__ __forceinline__ float pcalc(float s1, float e1p, float e1n,
                                       float s2, float e2p, float e2n,
                                       uint32_t w, int bit) {
    float t = s1 + s2;
    float p = (t > 0.f) ? e1p * e2p : e1n * e2n;
    return ((w >> bit) & 1u) ? p : 0.f;
}
__device__ __forceinline__ void mma16816(float* c, const uint32_t* a,
                                         uint32_t b0, uint32_t b1) {
    asm volatile(
        "mma.sync.aligned.m16n8k16.row.col.f32.bf16.bf16.f32 "
        "{%0,%1,%2,%3}, {%4,%5,%6,%7}, {%8,%9}, {%0,%1,%2,%3};"
        : "+f"(c[0]), "+f"(c[1]), "+f"(c[2]), "+f"(c[3])
        : "r"(a[0]), "r"(a[1]), "r"(a[2]), "r"(a[3]), "r"(b0), "r"(b1));
}
__device__ __forceinline__ void ldsm4(uint32_t& r0, uint32_t& r1,
                                      uint32_t& r2, uint32_t& r3, uint32_t a) {
    asm volatile("ldmatrix.sync.aligned.m8n8.x4.shared.b16 {%0,%1,%2,%3}, [%4];"
                 : "=r"(r0), "=r"(r1), "=r"(r2), "=r"(r3) : "r"(a));
}
__device__ __forceinline__ uint32_t smem_u32(const void* p) {
    uint32_t a;
    asm("{ .reg .u64 t; cvta.to.shared.u64 t, %1; cvt.u32.u64 %0, t; }"
        : "=r"(a) : "l"(p));
    return a;
}
#define CP16(dst, src) asm volatile("cp.async.cg.shared.global [%0], [%1], 16;" :: "r"(dst), "l"(src) : "memory")
#define CP_COMMIT()    asm volatile("cp.async.commit_group;" ::: "memory")
#define CP_WAIT0()     asm volatile("cp.async.wait_group 0;" ::: "memory")

// ---------------------------------------------------------------------------
// Kernel A (fused prep): compact (DRAM-bound) + wh (FMA-bound), interleaved
// 4:1 by blockIdx so every wave overlaps both pipes.
//   blockIdx.x % 5 == 0  -> wh CTA   (512 total)
//   else                 -> compact  (2048 total)
// ---------------------------------------------------------------------------
__global__ __launch_bounds__(256) void prep_kernel(const int*   __restrict__ adj,
                                                   const float* __restrict__ h,
                                                   const float* __restrict__ W,
                                                   const float* __restrict__ a) {
    __shared__ float Wt[FIN][68];
    __shared__ float Tr[64][33];
    int tid = threadIdx.x;

    if (blockIdx.x % 5 != 0) {
        // ================= compact branch =================
        int cb   = blockIdx.x - blockIdx.x / 5 - 1;       // 0..2047
        int warp = (cb * 256 + tid) >> 5;                 // row 0..16383
        int lane = tid & 31;
        const int4* rp = (const int4*)(adj + (size_t)warp * NN) + lane;
        uint4*      bp = (uint4*)(g_bm + (size_t)warp * 64);
#pragma unroll
        for (int r = 0; r < 16; r++) {
            int4 v = __ldg(rp + r * 32);
            uint32_t b0 = __ballot_sync(0xffffffffu, v.x != 0);
            uint32_t b1 = __ballot_sync(0xffffffffu, v.y != 0);
            uint32_t b2 = __ballot_sync(0xffffffffu, v.z != 0);
            uint32_t b3 = __ballot_sync(0xffffffffu, v.w != 0);
            if (lane == 0) bp[r] = make_uint4(b0, b1, b2, b3);
        }
        return;
    }

    // ================= wh branch =================
    int wb = blockIdx.x / 5;                              // 0..511
    for (int idx = tid; idx < FOUT * FIN; idx += 256) {
        int o = idx >> 7, f = idx & 127;
        Wt[f][o] = W[idx];
    }
    __syncthreads();

    int row0 = wb * 32;
    int rg = tid >> 4, cg = tid & 15;
    int r0 = row0 + rg * 2;
    int c0 = cg * 4;

    float acc[2][4] = {};
    const float* hp = h + (size_t)r0 * FIN;
    float4 hc0 = __ldg((const float4*)hp);
    float4 hc1 = __ldg((const float4*)(hp + FIN));
#pragma unroll 4
    for (int f = 0; f < FIN; f += 4) {
        float4 hn0, hn1;
        if (f + 4 < FIN) {
            hn0 = __ldg((const float4*)(hp + f + 4));
            hn1 = __ldg((const float4*)(hp + FIN + f + 4));
        }
        float4 wv0 = *(const float4*)&Wt[f + 0][c0];
        float4 wv1 = *(const float4*)&Wt[f + 1][c0];
        float4 wv2 = *(const float4*)&Wt[f + 2][c0];
        float4 wv3 = *(const float4*)&Wt[f + 3][c0];
        acc[0][0] += hc0.x * wv0.x + hc0.y * wv1.x + hc0.z * wv2.x + hc0.w * wv3.x;
        acc[0][1] += hc0.x * wv0.y + hc0.y * wv1.y + hc0.z * wv2.y + hc0.w * wv3.y;
        acc[0][2] += hc0.x * wv0.z + hc0.y * wv1.z + hc0.z * wv2.z + hc0.w * wv3.z;
        acc[0][3] += hc0.x * wv0.w + hc0.y * wv1.w + hc0.z * wv2.w + hc0.w * wv3.w;
        acc[1][0] += hc1.x * wv0.x + hc1.y * wv1.x + hc1.z * wv2.x + hc1.w * wv3.x;
        acc[1][1] += hc1.x * wv0.y + hc1.y * wv1.y + hc1.z * wv2.y + hc1.w * wv3.y;
        acc[1][2] += hc1.x * wv0.z + hc1.y * wv1.z + hc1.z * wv2.z + hc1.w * wv3.z;
        acc[1][3] += hc1.x * wv0.w + hc1.y * wv1.w + hc1.z * wv2.w + hc1.w * wv3.w;
        hc0 = hn0; hc1 = hn1;
    }

    float a1x = __ldg(&a[c0]),          a1y = __ldg(&a[c0 + 1]);
    float a1z = __ldg(&a[c0 + 2]),      a1w = __ldg(&a[c0 + 3]);
    float a2x = __ldg(&a[64 + c0]),     a2y = __ldg(&a[64 + c0 + 1]);
    float a2z = __ldg(&a[64 + c0 + 2]), a2w = __ldg(&a[64 + c0 + 3]);

#pragma unroll
    for (int k = 0; k < 2; k++) {
        float t1 = acc[k][0] * a1x + acc[k][1] * a1y + acc[k][2] * a1z + acc[k][3] * a1w;
        float t2 = acc[k][0] * a2x + acc[k][1] * a2y + acc[k][2] * a2z + acc[k][3] * a2w;
#pragma unroll
        for (int ofs = 8; ofs >= 1; ofs >>= 1) {
            t1 += __shfl_xor_sync(0xffffffffu, t1, ofs);
            t2 += __shfl_xor_sync(0xffffffffu, t2, ofs);
        }
        if (cg == 0) {
            g_s1[r0 + k] = t1;
            g_s2[r0 + k] = t2;
            g_e1[r0 + k] = make_float2(fexp(t1), fexp(0.2f * t1));
            g_e2[r0 + k] = make_float2(fexp(t2), fexp(0.2f * t2));
        }
#pragma unroll
        for (int q = 0; q < 4; q++) Tr[c0 + q][rg * 2 + k] = acc[k][q];
    }
    __syncthreads();

    {
        int c  = tid >> 2;
        int jl = (tid & 3) * 8;
        int bb = row0 >> 11;
        int jb = row0 & 2047;
        float v[8];
#pragma unroll
        for (int q = 0; q < 8; q++) v[q] = Tr[c][jl + q];
        uint32_t hu[4], lu[4];
#pragma unroll
        for (int q = 0; q < 4; q++)
            split2(v[2 * q], v[2 * q + 1], hu[q], lu[q]);
        size_t dst = ((size_t)bb * 64 + c) * NN + jb + jl;
        *(uint4*)(g_Vth + dst) = make_uint4(hu[0], hu[1], hu[2], hu[3]);
        *(uint4*)(g_Vtl + dst) = make_uint4(lu[0], lu[1], lu[2], lu[3]);
    }
}

// ---------------------------------------------------------------------------
// Kernel 2: attention partial. Grid (32, 8, 2): CTA = 64 i x 1024 j.
// Factorized exp, ldmatrix B fragments, cp.async V, bitmask register-
// prefetched. 3-MMA bf16 hi/lo compensation.
// ---------------------------------------------------------------------------
#define SM_VH(buf) ((buf) * 9216)              // 2 x 64x72 bf16
#define SM_VL(buf) (18432 + (buf) * 9216)
#define SM_E2      36864                       // float2[1024]
#define SM_S2      45056                       // float[1024]
#define SM_TOTAL   49152

__global__ __launch_bounds__(128, 4) void attn_kernel() {
    extern __shared__ __align__(16) char sm[];
    float* sE2 = (float*)(sm + SM_E2);
    float* sS2 = (float*)(sm + SM_S2);
    uint32_t sb = smem_u32(sm);

    int tid  = threadIdx.x;
    int w    = tid >> 5;
    int lane = tid & 31;
    int g    = lane >> 2;
    int t    = lane & 3;
    int th   = t >> 1;
    int b    = blockIdx.y;
    int i0   = blockIdx.x * 64;
    int jh   = blockIdx.z;

    // ---- preload e2/s2 tables into smem ----
    {
        const float4* e2src = (const float4*)(g_e2 + b * NN + jh * 1024);
        float4*       e2dst = (float4*)sE2;
#pragma unroll
        for (int k = 0; k < 4; k++) e2dst[tid + k * 128] = e2src[tid + k * 128];
        const float4* s2src = (const float4*)(g_s2 + b * NN + jh * 1024);
        float4*       s2dst = (float4*)sS2;
#pragma unroll
        for (int k = 0; k < 2; k++) s2dst[tid + k * 128] = s2src[tid + k * 128];
    }

    int    ilg = w * 16 + g;
    float  s1g  = g_s1[b * NN + i0 + ilg];
    float  s1g8 = g_s1[b * NN + i0 + ilg + 8];
    float2 e1g  = g_e1[b * NN + i0 + ilg];
    float2 e1g8 = g_e1[b * NN + i0 + ilg + 8];

    const uint4* bmp  = (const uint4*)(g_bm + (size_t)(b * NN + i0 + ilg) * 64 + jh * 32);
    const uint4* bmp8 = (const uint4*)(g_bm + (size_t)(b * NN + i0 + ilg + 8) * 64 + jh * 32);
    uint4 curg  = __ldg(bmp);
    uint4 curg8 = __ldg(bmp8);
    uint4 nxtg  = curg, nxtg8 = curg8;

    const __nv_bfloat16* vhb = g_Vth + (size_t)b * 64 * NN + jh * 1024;
    const __nv_bfloat16* vlb = g_Vtl + (size_t)b * 64 * NN + jh * 1024;

    uint32_t lsm_off = (((lane >> 4) & 1) * 8 + (lane & 7)) * 144
                     + ((lane >> 3) & 1) * 16;

    float C[8][4] = {};
    float part_g = 0.f, part_g8 = 0.f;

    // issue V tile 0
#pragma unroll
    for (int q = 0; q < 4; q++) {
        int c = tid + q * 128;
        int r = c >> 3, kc = (c & 7) * 8;
        CP16(sb + SM_VH(0) + r * 144 + kc * 2, vhb + (size_t)r * NN + kc);
        CP16(sb + SM_VL(0) + r * 144 + kc * 2, vlb + (size_t)r * NN + kc);
    }
    CP_COMMIT();
    __syncthreads();   // e2/s2 visible

    uint32_t wAg = 0, wBg = 0, wAg8 = 0, wBg8 = 0;

    for (int it = 0; it < 16; ++it) {
        int buf = it & 1;
        int j0  = it * 64;

        if ((it & 1) == 0) {
            if (it > 0) { curg = nxtg; curg8 = nxtg8; }
            wAg  = (t & 1) ? curg.z  : curg.x;
            wBg  = (t & 1) ? curg.w  : curg.y;
            wAg8 = (t & 1) ? curg8.z : curg8.x;
            wBg8 = (t & 1) ? curg8.w : curg8.y;
        }
        int base16 = (it & 1) * 16;

        // ---- stage 1: P A-fragments (factorized exp) ----
        uint32_t aH[4][4], aL[4][4];
#pragma unroll
        for (int ks = 0; ks < 4; ks++) {
            int jb = j0 + ks * 16 + 2 * t;
            int b0 = base16 + 4 * ks + th;
            float2 sA = *(const float2*)&sS2[jb];
            float2 sB = *(const float2*)&sS2[jb + 8];
            float4 eA = *(const float4*)&sE2[2 * jb];
            float4 eB = *(const float4*)&sE2[2 * (jb + 8)];

            float p00 = pcalc(s1g,  e1g.x,  e1g.y,  sA.x, eA.x, eA.y, wAg,  b0);
            float p01 = pcalc(s1g,  e1g.x,  e1g.y,  sA.y, eA.z, eA.w, wBg,  b0);
            float p02 = pcalc(s1g,  e1g.x,  e1g.y,  sB.x, eB.x, eB.y, wAg,  b0 + 2);
            float p03 = pcalc(s1g,  e1g.x,  e1g.y,  sB.y, eB.z, eB.w, wBg,  b0 + 2);
            float p10 = pcalc(s1g8, e1g8.x, e1g8.y, sA.x, eA.x, eA.y, wAg8, b0);
            float p11 = pcalc(s1g8, e1g8.x, e1g8.y, sA.y, eA.z, eA.w, wBg8, b0);
            float p12 = pcalc(s1g8, e1g8.x, e1g8.y, sB.x, eB.x, eB.y, wAg8, b0 + 2);
            float p13 = pcalc(s1g8, e1g8.x, e1g8.y, sB.y, eB.z, eB.w, wBg8, b0 + 2);

            part_g  += (p00 + p01) + (p02 + p03);
            part_g8 += (p10 + p11) + (p12 + p13);

            splitT(p00, p01, aH[ks][0], aL[ks][0]);
            splitT(p10, p11, aH[ks][1], aL[ks][1]);
            splitT(p02, p03, aH[ks][2], aL[ks][2]);
            splitT(p12, p13, aH[ks][3], aL[ks][3]);
        }

        CP_WAIT0();
        __syncthreads();

        // issue next V tile
        if (it + 1 < 16) {
            int jn = j0 + 64;
#pragma unroll
            for (int q = 0; q < 4; q++) {
                int c = tid + q * 128;
                int r = c >> 3, kc = (c & 7) * 8;
                CP16(sb + SM_VH(1 - buf) + r * 144 + kc * 2,
                     vhb + (size_t)r * NN + jn + kc);
                CP16(sb + SM_VL(1 - buf) + r * 144 + kc * 2,
                     vlb + (size_t)r * NN + jn + kc);
            }
            CP_COMMIT();
        }
        // prefetch next bitmask group
        if ((it & 1) == 0 && it + 2 < 16) {
            int grp = (it >> 1) + 1;
            nxtg  = __ldg(bmp + grp);
            nxtg8 = __ldg(bmp8 + grp);
        }

        // ---- MMAs via ldmatrix: Ph*Vh, Pl*Vh, Ph*Vl ----
        uint32_t baseH = sb + SM_VH(buf) + lsm_off;
        uint32_t baseL = sb + SM_VL(buf) + lsm_off;
#pragma unroll
        for (int ks = 0; ks < 4; ks++) {
#pragma unroll
            for (int p = 0; p < 4; p++) {
                uint32_t bh0, bh1, bh2, bh3, bl0, bl1, bl2, bl3;
                ldsm4(bh0, bh1, bh2, bh3, baseH + p * 2304 + ks * 32);
                ldsm4(bl0, bl1, bl2, bl3, baseL + p * 2304 + ks * 32);
                mma16816(C[2 * p],     aH[ks], bh0, bh1);
                mma16816(C[2 * p + 1], aH[ks], bh2, bh3);
                mma16816(C[2 * p],     aL[ks], bh0, bh1);
                mma16816(C[2 * p + 1], aL[ks], bh2, bh3);
                mma16816(C[2 * p],     aH[ks], bl0, bl1);
                mma16816(C[2 * p + 1], aH[ks], bl2, bl3);
            }
        }
    }

    // ---- partial denominators (4-lane quads) ----
    part_g  += __shfl_xor_sync(0xffffffffu, part_g, 1);
    part_g  += __shfl_xor_sync(0xffffffffu, part_g, 2);
    part_g8 += __shfl_xor_sync(0xffffffffu, part_g8, 1);
    part_g8 += __shfl_xor_sync(0xffffffffu, part_g8, 2);
    size_t growb = (size_t)b * NN + i0 + ilg;
    if (t == 0) {
        g_pd[(size_t)jh * (B * NN) + growb]     = part_g;
        g_pd[(size_t)jh * (B * NN) + growb + 8] = part_g8;
    }

    // ---- store partial C ----
    float* pc = g_pC + ((size_t)jh * (B * NN) + growb) * FOUT + 2 * t;
#pragma unroll
    for (int ns = 0; ns < 8; ns++) {
        *(float2*)(pc + 8 * ns)       = make_float2(C[ns][0], C[ns][1]);
        *(float2*)(pc + 8 * ns + 512) = make_float2(C[ns][2], C[ns][3]);
    }
}

// ---------------------------------------------------------------------------
// Kernel 3: combine halves + normalize. 2 float4 chunks/thread, loads upfront.
// ---------------------------------------------------------------------------
__global__ __launch_bounds__(256) void combine_kernel(float* __restrict__ out) {
    int gid = blockIdx.x * 256 + threadIdx.x;      // 131072
    int row = gid >> 3;
    int q   = (gid & 7) * 8;
    const float* p0 = g_pC + (size_t)row * FOUT + q;
    const float* p1 = g_pC + (size_t)(B * NN + row) * FOUT + q;
    float4 a0 = *(const float4*)p0;
    float4 a1 = *(const float4*)(p0 + 4);
    float4 b0 = *(const float4*)p1;
    float4 b1 = *(const float4*)(p1 + 4);
    float  d0 = g_pd[row];
    float  d1 = g_pd[B * NN + row];
    float inv = __fdividef(1.0f, d0 + d1);
    float4 o0 = make_float4((a0.x + b0.x) * inv, (a0.y + b0.y) * inv,
                            (a0.z + b0.z) * inv, (a0.w + b0.w) * inv);
    float4 o1 = make_float4((a1.x + b1.x) * inv, (a1.y + b1.y) * inv,
                            (a1.z + b1.z) * inv, (a1.w + b1.w) * inv);
    float* op = out + (size_t)row * FOUT + q;
    *(float4*)op       = o0;
    *(float4*)(op + 4) = o1;
}

// ---------------------------------------------------------------------------
extern "C" void kernel_launch(void* const* d_in, const int* in_sizes, int n_in,
                              void* d_out, int out_size) {
    const float* h   = (const float*)d_in[0];
    const int*   adj = (const int*)d_in[1];
    const float* W   = (const float*)d_in[2];
    const float* a   = (const float*)d_in[3];
    float* out = (float*)d_out;

    static int smem_set = 0;
    if (!smem_set) {
        cudaFuncSetAttribute(attn_kernel,
                             cudaFuncAttributeMaxDynamicSharedMemorySize, SM_TOTAL);
        smem_set = 1;
    }

    prep_kernel<<<2560, 256>>>(adj, h, W, a);
    attn_kernel<<<dim3(NN / 64, B, 2), 128, SM_TOTAL>>>();
    combine_kernel<<<(B * NN * 8) / 256, 256>>>(out);
}

// round 10
// speedup vs baseline: 2.6191x; 1.0029x over previous
#include <cuda_runtime.h>
#include <cuda_bf16.h>
#include <cstdint>

#define B    8
#define NN   2048
#define FIN  128
#define FOUT 64

// Scratch (no cudaMalloc allowed)
__device__ __align__(16) __nv_bfloat16 g_Vth[B * FOUT * NN];  // [b][n][j] hi
__device__ __align__(16) __nv_bfloat16 g_Vtl[B * FOUT * NN];  // [b][n][j] lo
__device__ __align__(16) float    g_s1[B * NN];
__device__ __align__(16) float    g_s2[B * NN];
__device__ __align__(16) float2   g_e1[B * NN];               // (exp(s1), exp(.2 s1))
__device__ __align__(16) float2   g_e2[B * NN];               // (exp(s2), exp(.2 s2))
__device__ __align__(16) uint32_t g_bm[B * NN * 64];          // interleaved bits
__device__ __align__(16) float    g_pC[2 * B * NN * FOUT];    // partial C
__device__ __align__(16) float    g_pd[2 * B * NN];           // partial denom

// ---------------------------------------------------------------------------
__device__ __forceinline__ float fexp(float x) {   // FMA-pipe exp, rel ~2e-6
    float z  = fmaf(x, 1.4426950408889634f, 12582912.0f);
    int   n  = __float_as_int(z) - 0x4B400000;
    float zf = z - 12582912.0f;
    float r  = fmaf(zf, -0.6931471805599453f, x);
    float p  =        1.3888889e-3f;
    p = fmaf(p, r,    8.3333333e-3f);
    p = fmaf(p, r,    4.1666668e-2f);
    p = fmaf(p, r,    1.6666667e-1f);
    p = fmaf(p, r,    5.0000000e-1f);
    p = fmaf(p, r,    1.0f);
    p = fmaf(p, r,    1.0f);
    return __int_as_float(__float_as_int(p) + (n << 23));
}

__device__ __forceinline__ uint32_t b2u(__nv_bfloat162 v) {
    return *reinterpret_cast<uint32_t*>(&v);
}
__device__ __forceinline__ void split2(float x0, float x1,
                                       uint32_t& hi, uint32_t& lo) {
    __nv_bfloat162 h = __floats2bfloat162_rn(x0, x1);
    float r0 = x0 - __bfloat162float(h.x);
    float r1 = x1 - __bfloat162float(h.y);
    hi = b2u(h);
    lo = b2u(__floats2bfloat162_rn(r0, r1));
}
// trunc-split (exact residual), PRMT pack, ALU-pipe heavy
__device__ __forceinline__ void splitT(float p0, float p1,
                                       uint32_t& hi, uint32_t& lo) {
    uint32_t i0 = __float_as_uint(p0), i1 = __float_as_uint(p1);
    float r0 = p0 - __uint_as_float(i0 & 0xffff0000u);
    float r1 = p1 - __uint_as_float(i1 & 0xffff0000u);
    asm("prmt.b32 %0, %1, %2, 0x7632;" : "=r"(hi) : "r"(i0), "r"(i1));
    lo = b2u(__floats2bfloat162_rn(r0, r1));
}
// factorized masked lrelu-exp
__device__ __forceinline__ float pcalc(float s1, float e1p, float e1n,
                                       float s2, float e2p, float e2n,
                                       uint32_t w, int bit) {
    float t = s1 + s2;
    float p = (t > 0.f) ? e1p * e2p : e1n * e2n;
    return ((w >> bit) & 1u) ? p : 0.f;
}
__device__ __forceinline__ void mma16816(float* c, const uint32_t* a,
                                         uint32_t b0, uint32_t b1) {
    asm volatile(
        "mma.sync.aligned.m16n8k16.row.col.f32.bf16.bf16.f32 "
        "{%0,%1,%2,%3}, {%4,%5,%6,%7}, {%8,%9}, {%0,%1,%2,%3};"
        : "+f"(c[0]), "+f"(c[1]), "+f"(c[2]), "+f"(c[3])
        : "r"(a[0]), "r"(a[1]), "r"(a[2]), "r"(a[3]), "r"(b0), "r"(b1));
}
__device__ __forceinline__ void ldsm4(uint32_t& r0, uint32_t& r1,
                                      uint32_t& r2, uint32_t& r3, uint32_t a) {
    asm volatile("ldmatrix.sync.aligned.m8n8.x4.shared.b16 {%0,%1,%2,%3}, [%4];"
                 : "=r"(r0), "=r"(r1), "=r"(r2), "=r"(r3) : "r"(a));
}
__device__ __forceinline__ uint32_t smem_u32(const void* p) {
    uint32_t a;
    asm("{ .reg .u64 t; cvta.to.shared.u64 t, %1; cvt.u32.u64 %0, t; }"
        : "=r"(a) : "l"(p));
    return a;
}
#define CP16(dst, src) asm volatile("cp.async.cg.shared.global [%0], [%1], 16;" :: "r"(dst), "l"(src) : "memory")
#define CP_COMMIT()    asm volatile("cp.async.commit_group;" ::: "memory")
#define CP_WAIT0()     asm volatile("cp.async.wait_group 0;" ::: "memory")

// ---------------------------------------------------------------------------
// Kernel A (fused prep): compact (DRAM-bound) + wh (FMA-bound), interleaved
// 4:1 by blockIdx. Smem: Wt/Tr UNIONED (34 KB -> 6 CTAs/SM). Compact loads
// batched 4-deep for MLP=4.
// ---------------------------------------------------------------------------
__global__ __launch_bounds__(256) void prep_kernel(const int*   __restrict__ adj,
                                                   const float* __restrict__ h,
                                                   const float* __restrict__ W,
                                                   const float* __restrict__ a) {
    __shared__ __align__(16) char smu[FIN * 68 * 4];   // union: Wt then Tr
    float (*Wt)[68] = (float(*)[68])smu;
    float (*Tr)[33] = (float(*)[33])smu;
    int tid = threadIdx.x;

    if (blockIdx.x % 5 != 0) {
        // ================= compact branch =================
        int cb   = blockIdx.x - blockIdx.x / 5 - 1;       // 0..2047
        int warp = (cb * 256 + tid) >> 5;                 // row 0..16383
        int lane = tid & 31;
        const int4* rp = (const int4*)(adj + (size_t)warp * NN) + lane;
        uint4*      bp = (uint4*)(g_bm + (size_t)warp * 64);
#pragma unroll
        for (int rr = 0; rr < 4; rr++) {
            int4 v0 = __ldg(rp + (rr * 4 + 0) * 32);      // 4 independent LDG.128
            int4 v1 = __ldg(rp + (rr * 4 + 1) * 32);
            int4 v2 = __ldg(rp + (rr * 4 + 2) * 32);
            int4 v3 = __ldg(rp + (rr * 4 + 3) * 32);
            uint32_t a0 = __ballot_sync(0xffffffffu, v0.x != 0);
            uint32_t a1 = __ballot_sync(0xffffffffu, v0.y != 0);
            uint32_t a2 = __ballot_sync(0xffffffffu, v0.z != 0);
            uint32_t a3 = __ballot_sync(0xffffffffu, v0.w != 0);
            uint32_t b0 = __ballot_sync(0xffffffffu, v1.x != 0);
            uint32_t b1 = __ballot_sync(0xffffffffu, v1.y != 0);
            uint32_t b2 = __ballot_sync(0xffffffffu, v1.z != 0);
            uint32_t b3 = __ballot_sync(0xffffffffu, v1.w != 0);
            uint32_t c0 = __ballot_sync(0xffffffffu, v2.x != 0);
            uint32_t c1 = __ballot_sync(0xffffffffu, v2.y != 0);
            uint32_t c2 = __ballot_sync(0xffffffffu, v2.z != 0);
            uint32_t c3 = __ballot_sync(0xffffffffu, v2.w != 0);
            uint32_t d0 = __ballot_sync(0xffffffffu, v3.x != 0);
            uint32_t d1 = __ballot_sync(0xffffffffu, v3.y != 0);
            uint32_t d2 = __ballot_sync(0xffffffffu, v3.z != 0);
            uint32_t d3 = __ballot_sync(0xffffffffu, v3.w != 0);
            if (lane == 0) {
                bp[rr * 4 + 0] = make_uint4(a0, a1, a2, a3);
                bp[rr * 4 + 1] = make_uint4(b0, b1, b2, b3);
                bp[rr * 4 + 2] = make_uint4(c0, c1, c2, c3);
                bp[rr * 4 + 3] = make_uint4(d0, d1, d2, d3);
            }
        }
        return;
    }

    // ================= wh branch =================
    int wb = blockIdx.x / 5;                              // 0..511
    for (int idx = tid; idx < FOUT * FIN; idx += 256) {
        int o = idx >> 7, f = idx & 127;
        Wt[f][o] = W[idx];
    }
    __syncthreads();

    int row0 = wb * 32;
    int rg = tid >> 4, cg = tid & 15;
    int r0 = row0 + rg * 2;
    int c0 = cg * 4;

    float acc[2][4] = {};
    const float* hp = h + (size_t)r0 * FIN;
    float4 hc0 = __ldg((const float4*)hp);
    float4 hc1 = __ldg((const float4*)(hp + FIN));
#pragma unroll 4
    for (int f = 0; f < FIN; f += 4) {
        float4 hn0, hn1;
        if (f + 4 < FIN) {
            hn0 = __ldg((const float4*)(hp + f + 4));
            hn1 = __ldg((const float4*)(hp + FIN + f + 4));
        }
        float4 wv0 = *(const float4*)&Wt[f + 0][c0];
        float4 wv1 = *(const float4*)&Wt[f + 1][c0];
        float4 wv2 = *(const float4*)&Wt[f + 2][c0];
        float4 wv3 = *(const float4*)&Wt[f + 3][c0];
        acc[0][0] += hc0.x * wv0.x + hc0.y * wv1.x + hc0.z * wv2.x + hc0.w * wv3.x;
        acc[0][1] += hc0.x * wv0.y + hc0.y * wv1.y + hc0.z * wv2.y + hc0.w * wv3.y;
        acc[0][2] += hc0.x * wv0.z + hc0.y * wv1.z + hc0.z * wv2.z + hc0.w * wv3.z;
        acc[0][3] += hc0.x * wv0.w + hc0.y * wv1.w + hc0.z * wv2.w + hc0.w * wv3.w;
        acc[1][0] += hc1.x * wv0.x + hc1.y * wv1.x + hc1.z * wv2.x + hc1.w * wv3.x;
        acc[1][1] += hc1.x * wv0.y + hc1.y * wv1.y + hc1.z * wv2.y + hc1.w * wv3.y;
        acc[1][2] += hc1.x * wv0.z + hc1.y * wv1.z + hc1.z * wv2.z + hc1.w * wv3.z;
        acc[1][3] += hc1.x * wv0.w + hc1.y * wv1.w + hc1.z * wv2.w + hc1.w * wv3.w;
        hc0 = hn0; hc1 = hn1;
    }
    __syncthreads();   // Wt dead from here; Tr may alias it

    float a1x = __ldg(&a[c0]),          a1y = __ldg(&a[c0 + 1]);
    float a1z = __ldg(&a[c0 + 2]),      a1w = __ldg(&a[c0 + 3]);
    float a2x = __ldg(&a[64 + c0]),     a2y = __ldg(&a[64 + c0 + 1]);
    float a2z = __ldg(&a[64 + c0 + 2]), a2w = __ldg(&a[64 + c0 + 3]);

#pragma unroll
    for (int k = 0; k < 2; k++) {
        float t1 = acc[k][0] * a1x + acc[k][1] * a1y + acc[k][2] * a1z + acc[k][3] * a1w;
        float t2 = acc[k][0] * a2x + acc[k][1] * a2y + acc[k][2] * a2z + acc[k][3] * a2w;
#pragma unroll
        for (int ofs = 8; ofs >= 1; ofs >>= 1) {
            t1 += __shfl_xor_sync(0xffffffffu, t1, ofs);
            t2 += __shfl_xor_sync(0xffffffffu, t2, ofs);
        }
        if (cg == 0) {
            g_s1[r0 + k] = t1;
            g_s2[r0 + k] = t2;
            g_e1[r0 + k] = make_float2(fexp(t1), fexp(0.2f * t1));
            g_e2[r0 + k] = make_float2(fexp(t2), fexp(0.2f * t2));
        }
#pragma unroll
        for (int q = 0; q < 4; q++) Tr[c0 + q][rg * 2 + k] = acc[k][q];
    }
    __syncthreads();

    {
        int c  = tid >> 2;
        int jl = (tid & 3) * 8;
        int bb = row0 >> 11;
        int jb = row0 & 2047;
        float v[8];
#pragma unroll
        for (int q = 0; q < 8; q++) v[q] = Tr[c][jl + q];
        uint32_t hu[4], lu[4];
#pragma unroll
        for (int q = 0; q < 4; q++)
            split2(v[2 * q], v[2 * q + 1], hu[q], lu[q]);
        size_t dst = ((size_t)bb * 64 + c) * NN + jb + jl;
        *(uint4*)(g_Vth + dst) = make_uint4(hu[0], hu[1], hu[2], hu[3]);
        *(uint4*)(g_Vtl + dst) = make_uint4(lu[0], lu[1], lu[2], lu[3]);
    }
}

// ---------------------------------------------------------------------------
// Kernel 2: attention partial. Grid (32, 8, 2): CTA = 64 i x 1024 j.
// Factorized exp, ldmatrix B fragments, cp.async V, bitmask register-
// prefetched. 3-MMA bf16 hi/lo compensation.
// ---------------------------------------------------------------------------
#define SM_VH(buf) ((buf) * 9216)              // 2 x 64x72 bf16
#define SM_VL(buf) (18432 + (buf) * 9216)
#define SM_E2      36864                       // float2[1024]
#define SM_S2      45056                       // float[1024]
#define SM_TOTAL   49152

__global__ __launch_bounds__(128, 4) void attn_kernel() {
    extern __shared__ __align__(16) char sm[];
    float* sE2 = (float*)(sm + SM_E2);
    float* sS2 = (float*)(sm + SM_S2);
    uint32_t sb = smem_u32(sm);

    int tid  = threadIdx.x;
    int w    = tid >> 5;
    int lane = tid & 31;
    int g    = lane >> 2;
    int t    = lane & 3;
    int th   = t >> 1;
    int b    = blockIdx.y;
    int i0   = blockIdx.x * 64;
    int jh   = blockIdx.z;

    // ---- preload e2/s2 tables into smem ----
    {
        const float4* e2src = (const float4*)(g_e2 + b * NN + jh * 1024);
        float4*       e2dst = (float4*)sE2;
#pragma unroll
        for (int k = 0; k < 4; k++) e2dst[tid + k * 128] = e2src[tid + k * 128];
        const float4* s2src = (const float4*)(g_s2 + b * NN + jh * 1024);
        float4*       s2dst = (float4*)sS2;
#pragma unroll
        for (int k = 0; k < 2; k++) s2dst[tid + k * 128] = s2src[tid + k * 128];
    }

    int    ilg = w * 16 + g;
    float  s1g  = g_s1[b * NN + i0 + ilg];
    float  s1g8 = g_s1[b * NN + i0 + ilg + 8];
    float2 e1g  = g_e1[b * NN + i0 + ilg];
    float2 e1g8 = g_e1[b * NN + i0 + ilg + 8];

    const uint4* bmp  = (const uint4*)(g_bm + (size_t)(b * NN + i0 + ilg) * 64 + jh * 32);
    const uint4* bmp8 = (const uint4*)(g_bm + (size_t)(b * NN + i0 + ilg + 8) * 64 + jh * 32);
    uint4 curg  = __ldg(bmp);
    uint4 curg8 = __ldg(bmp8);
    uint4 nxtg  = curg, nxtg8 = curg8;

    const __nv_bfloat16* vhb = g_Vth + (size_t)b * 64 * NN + jh * 1024;
    const __nv_bfloat16* vlb = g_Vtl + (size_t)b * 64 * NN + jh * 1024;

    uint32_t lsm_off = (((lane >> 4) & 1) * 8 + (lane & 7)) * 144
                     + ((lane >> 3) & 1) * 16;

    float C[8][4] = {};
    float part_g = 0.f, part_g8 = 0.f;

    // issue V tile 0
#pragma unroll
    for (int q = 0; q < 4; q++) {
        int c = tid + q * 128;
        int r = c >> 3, kc = (c & 7) * 8;
        CP16(sb + SM_VH(0) + r * 144 + kc * 2, vhb + (size_t)r * NN + kc);
        CP16(sb + SM_VL(0) + r * 144 + kc * 2, vlb + (size_t)r * NN + kc);
    }
    CP_COMMIT();
    __syncthreads();   // e2/s2 visible

    uint32_t wAg = 0, wBg = 0, wAg8 = 0, wBg8 = 0;

    for (int it = 0; it < 16; ++it) {
        int buf = it & 1;
        int j0  = it * 64;

        if ((it & 1) == 0) {
            if (it > 0) { curg = nxtg; curg8 = nxtg8; }
            wAg  = (t & 1) ? curg.z  : curg.x;
            wBg  = (t & 1) ? curg.w  : curg.y;
            wAg8 = (t & 1) ? curg8.z : curg8.x;
            wBg8 = (t & 1) ? curg8.w : curg8.y;
        }
        int base16 = (it & 1) * 16;

        // ---- stage 1: P A-fragments (factorized exp) ----
        uint32_t aH[4][4], aL[4][4];
#pragma unroll
        for (int ks = 0; ks < 4; ks++) {
            int jb = j0 + ks * 16 + 2 * t;
            int b0 = base16 + 4 * ks + th;
            float2 sA = *(const float2*)&sS2[jb];
            float2 sB = *(const float2*)&sS2[jb + 8];
            float4 eA = *(const float4*)&sE2[2 * jb];
            float4 eB = *(const float4*)&sE2[2 * (jb + 8)];

            float p00 = pcalc(s1g,  e1g.x,  e1g.y,  sA.x, eA.x, eA.y, wAg,  b0);
            float p01 = pcalc(s1g,  e1g.x,  e1g.y,  sA.y, eA.z, eA.w, wBg,  b0);
            float p02 = pcalc(s1g,  e1g.x,  e1g.y,  sB.x, eB.x, eB.y, wAg,  b0 + 2);
            float p03 = pcalc(s1g,  e1g.x,  e1g.y,  sB.y, eB.z, eB.w, wBg,  b0 + 2);
            float p10 = pcalc(s1g8, e1g8.x, e1g8.y, sA.x, eA.x, eA.y, wAg8, b0);
            float p11 = pcalc(s1g8, e1g8.x, e1g8.y, sA.y, eA.z, eA.w, wBg8, b0);
            float p12 = pcalc(s1g8, e1g8.x, e1g8.y, sB.x, eB.x, eB.y, wAg8, b0 + 2);
            float p13 = pcalc(s1g8, e1g8.x, e1g8.y, sB.y, eB.z, eB.w, wBg8, b0 + 2);

            part_g  += (p00 + p01) + (p02 + p03);
            part_g8 += (p10 + p11) + (p12 + p13);

            splitT(p00, p01, aH[ks][0], aL[ks][0]);
            splitT(p10, p11, aH[ks][1], aL[ks][1]);
            splitT(p02, p03, aH[ks][2], aL[ks][2]);
            splitT(p12, p13, aH[ks][3], aL[ks][3]);
        }

        CP_WAIT0();
        __syncthreads();

        // issue next V tile
        if (it + 1 < 16) {
            int jn = j0 + 64;
#pragma unroll
            for (int q = 0; q < 4; q++) {
                int c = tid + q * 128;
                int r = c >> 3, kc = (c & 7) * 8;
                CP16(sb + SM_VH(1 - buf) + r * 144 + kc * 2,
                     vhb + (size_t)r * NN + jn + kc);
                CP16(sb + SM_VL(1 - buf) + r * 144 + kc * 2,
                     vlb + (size_t)r * NN + jn + kc);
            }
            CP_COMMIT();
        }
        // prefetch next bitmask group
        if ((it & 1) == 0 && it + 2 < 16) {
            int grp = (it >> 1) + 1;
            nxtg  = __ldg(bmp + grp);
            nxtg8 = __ldg(bmp8 + grp);
        }

        // ---- MMAs via ldmatrix: Ph*Vh, Pl*Vh, Ph*Vl ----
        uint32_t baseH = sb + SM_VH(buf) + lsm_off;
        uint32_t baseL = sb + SM_VL(buf) + lsm_off;
#pragma unroll
        for (int ks = 0; ks < 4; ks++) {
#pragma unroll
            for (int p = 0; p < 4; p++) {
                uint32_t bh0, bh1, bh2, bh3, bl0, bl1, bl2, bl3;
                ldsm4(bh0, bh1, bh2, bh3, baseH + p * 2304 + ks * 32);
                ldsm4(bl0, bl1, bl2, bl3, baseL + p * 2304 + ks * 32);
                mma16816(C[2 * p],     aH[ks], bh0, bh1);
                mma16816(C[2 * p + 1], aH[ks], bh2, bh3);
                mma16816(C[2 * p],     aL[ks], bh0, bh1);
                mma16816(C[2 * p + 1], aL[ks], bh2, bh3);
                mma16816(C[2 * p],     aH[ks], bl0, bl1);
                mma16816(C[2 * p + 1], aH[ks], bl2, bl3);
            }
        }
    }

    // ---- partial denominators (4-lane quads) ----
    part_g  += __shfl_xor_sync(0xffffffffu, part_g, 1);
    part_g  += __shfl_xor_sync(0xffffffffu, part_g, 2);
    part_g8 += __shfl_xor_sync(0xffffffffu, part_g8, 1);
    part_g8 += __shfl_xor_sync(0xffffffffu, part_g8, 2);
    size_t growb = (size_t)b * NN + i0 + ilg;
    if (t == 0) {
        g_pd[(size_t)jh * (B * NN) + growb]     = part_g;
        g_pd[(size_t)jh * (B * NN) + growb + 8] = part_g8;
    }

    // ---- store partial C ----
    float* pc = g_pC + ((size_t)jh * (B * NN) + growb) * FOUT + 2 * t;
#pragma unroll
    for (int ns = 0; ns < 8; ns++) {
        *(float2*)(pc + 8 * ns)       = make_float2(C[ns][0], C[ns][1]);
        *(float2*)(pc + 8 * ns + 512) = make_float2(C[ns][2], C[ns][3]);
    }
}

// ---------------------------------------------------------------------------
// Kernel 3: combine halves + normalize. 2 float4 chunks/thread, loads upfront.
// ---------------------------------------------------------------------------
__global__ __launch_bounds__(256) void combine_kernel(float* __restrict__ out) {
    int gid = blockIdx.x * 256 + threadIdx.x;      // 131072
    int row = gid >> 3;
    int q   = (gid & 7) * 8;
    const float* p0 = g_pC + (size_t)row * FOUT + q;
    const float* p1 = g_pC + (size_t)(B * NN + row) * FOUT + q;
    float4 a0 = *(const float4*)p0;
    float4 a1 = *(const float4*)(p0 + 4);
    float4 b0 = *(const float4*)p1;
    float4 b1 = *(const float4*)(p1 + 4);
    float  d0 = g_pd[row];
    float  d1 = g_pd[B * NN + row];
    float inv = __fdividef(1.0f, d0 + d1);
    float4 o0 = make_float4((a0.x + b0.x) * inv, (a0.y + b0.y) * inv,
                            (a0.z + b0.z) * inv, (a0.w + b0.w) * inv);
    float4 o1 = make_float4((a1.x + b1.x) * inv, (a1.y + b1.y) * inv,
                            (a1.z + b1.z) * inv, (a1.w + b1.w) * inv);
    float* op = out + (size_t)row * FOUT + q;
    *(float4*)op       = o0;
    *(float4*)(op + 4) = o1;
}

// ---------------------------------------------------------------------------
extern "C" void kernel_launch(void* const* d_in, const int* in_sizes, int n_in,
                              void* d_out, int out_size) {
    const float* h   = (const float*)d_in[0];
    const int*   adj = (const int*)d_in[1];
    const float* W   = (const float*)d_in[2];
    const float* a   = (const float*)d_in[3];
    float* out = (float*)d_out;

    static int smem_set = 0;
    if (!smem_set) {
        cudaFuncSetAttribute(attn_kernel,
                             cudaFuncAttributeMaxDynamicSharedMemorySize, SM_TOTAL);
        smem_set = 1;
    }

    prep_kernel<<<2560, 256>>>(adj, h, W, a);
    attn_kernel<<<dim3(NN / 64, B, 2), 128, SM_TOTAL>>>();
    combine_kernel<<<(B * NN * 8) / 256, 256>>>(out);
}